// round 9
// baseline (speedup 1.0000x reference)
#include <cuda_runtime.h>
#include <cuda_bf16.h>
#include <cstdint>

#define B_ 2
#define S_ 2048
#define D_ 1024
#define H_ 16
#define DK_ 64
#define OUT_ELEMS (B_*S_*D_)           /* 4194304  */
#define ATT_ELEMS (B_*H_*S_*S_)        /* 134217728 */

// ---------------- scratch (device globals; no allocation allowed) ----------
__device__ float g_Q[B_*H_*S_*DK_];    // [b][h][s][d], pre-scaled by 1/8
__device__ float g_K[B_*H_*S_*DK_];
__device__ float g_V[B_*H_*S_*DK_];
__device__ float g_C[B_*S_*D_];        // context, token-major
__device__ float g_L[B_*H_*S_];        // softmax row sums

__device__ __forceinline__ uint32_t smem_u32(const void* p) {
    uint32_t a;
    asm("{ .reg .u64 t; cvta.to.shared.u64 t, %1; cvt.u32.u64 %0, t; }" : "=r"(a) : "l"(p));
    return a;
}

// ---------------- mma.sync primitives (baseline PTX, no 'a' features) ------
__device__ __forceinline__ void ldsm_x4(uint32_t (&r)[4], uint32_t addr) {
    asm volatile("ldmatrix.sync.aligned.m8n8.x4.shared.b16 {%0,%1,%2,%3}, [%4];"
        : "=r"(r[0]), "=r"(r[1]), "=r"(r[2]), "=r"(r[3]) : "r"(addr));
}
__device__ __forceinline__ void ldsm_x2(uint32_t (&r)[2], uint32_t addr) {
    asm volatile("ldmatrix.sync.aligned.m8n8.x2.shared.b16 {%0,%1}, [%2];"
        : "=r"(r[0]), "=r"(r[1]) : "r"(addr));
}
__device__ __forceinline__ void ldsm_x2t(uint32_t (&r)[2], uint32_t addr) {
    asm volatile("ldmatrix.sync.aligned.m8n8.x2.trans.shared.b16 {%0,%1}, [%2];"
        : "=r"(r[0]), "=r"(r[1]) : "r"(addr));
}
__device__ __forceinline__ void mma16816(float (&c)[4], const uint32_t (&a)[4],
                                         const uint32_t (&b)[2]) {
    asm volatile("mma.sync.aligned.m16n8k16.row.col.f32.bf16.bf16.f32 "
        "{%0,%1,%2,%3}, {%4,%5,%6,%7}, {%8,%9}, {%0,%1,%2,%3};"
        : "+f"(c[0]), "+f"(c[1]), "+f"(c[2]), "+f"(c[3])
        : "r"(a[0]), "r"(a[1]), "r"(a[2]), "r"(a[3]), "r"(b[0]), "r"(b[1]));
}
__device__ __forceinline__ uint32_t packbf(float lo, float hi) {
    uint32_t r;
    asm("cvt.rn.bf16x2.f32 %0, %1, %2;" : "=r"(r) : "f"(hi), "f"(lo));
    return r;
}
__device__ __forceinline__ float bf_round(float x) {
    return __bfloat162float(__float2bfloat16(x));
}
__device__ __forceinline__ void cvt4(uint2 &hi, uint2 &lo, float4 vv) {
    float v0 = vv.x, v1 = vv.y, v2 = vv.z, v3 = vv.w;
    __nv_bfloat16 h0 = __float2bfloat16(v0), h1 = __float2bfloat16(v1);
    __nv_bfloat16 h2 = __float2bfloat16(v2), h3 = __float2bfloat16(v3);
    __nv_bfloat162 hh0(h0, h1), hh1(h2, h3);
    __nv_bfloat162 ll0(__float2bfloat16(v0 - __bfloat162float(h0)),
                       __float2bfloat16(v1 - __bfloat162float(h1)));
    __nv_bfloat162 ll1(__float2bfloat16(v2 - __bfloat162float(h2)),
                       __float2bfloat16(v3 - __bfloat162float(h3)));
    hi = make_uint2(*(uint32_t*)&hh0, *(uint32_t*)&hh1);
    lo = make_uint2(*(uint32_t*)&ll0, *(uint32_t*)&ll1);
}

// ===========================================================================
// Split-bf16 tensor-core GEMM core (inlined by callers).
// C[m,n] = scale * sum_k X[m,k] * W[n,k]; mode 0 head-major, mode 1 row-major.
// ===========================================================================
#define PITCH 40
#define MAT_U (128*PITCH)
#define STAGE_U (4*MAT_U)
#define GT_SMEM (2*STAGE_U*2)

__device__ __forceinline__ size_t ymap(int m, int n, int mode) {
    if (mode == 0)
        return (((size_t)((m >> 11) * 16 + (n >> 6))) * 2048 + (m & 2047)) * 64 + (n & 63);
    return (size_t)m * 1024 + n;
}

__device__ __forceinline__ void gemm_core(
    const float* __restrict__ X, const float* __restrict__ W,
    float* __restrict__ Y, float scale, int mode, int bm, int bn,
    __nv_bfloat16* sh)
{
    const uint32_t sh0 = smem_u32(sh);
    const int t = threadIdx.x;
    const int warp = t >> 5, lane = t & 31;
    const int wm = (warp >> 1) * 32;
    const int wn = (warp & 1) * 64;
    const int lr = t >> 3, lc = (t & 7) * 4;

    float4 ra[4], rb[4];
    float acc[2][8][4];
    #pragma unroll
    for (int mt = 0; mt < 2; mt++)
        #pragma unroll
        for (int nt = 0; nt < 8; nt++)
            #pragma unroll
            for (int j = 0; j < 4; j++) acc[mt][nt][j] = 0.f;

    const int r8 = lane & 7, tl = lane >> 3;
    const uint32_t a_row = (uint32_t)(wm + (tl & 1) * 8 + r8);
    const uint32_t a_col = (uint32_t)((tl >> 1) * 16);
    const uint32_t b_row = (uint32_t)(wn + r8);
    const uint32_t b_col = (uint32_t)((tl & 1) * 16);

    #define GEMM_LDG(c) do {                                                     \
        const float* xp = X + (size_t)(bm + lr) * 1024 + (c) * 32 + lc;          \
        const float* wp = W + (size_t)(bn + lr) * 1024 + (c) * 32 + lc;          \
        _Pragma("unroll")                                                        \
        for (int p = 0; p < 4; p++) {                                            \
            ra[p] = *(const float4*)(xp + (size_t)p * 32 * 1024);                \
            rb[p] = *(const float4*)(wp + (size_t)p * 32 * 1024);                \
        }                                                                        \
    } while (0)

    #define GEMM_STS(s) do {                                                     \
        __nv_bfloat16* Ah = sh + (s) * STAGE_U;                                  \
        __nv_bfloat16* Al = Ah + MAT_U;                                          \
        __nv_bfloat16* Bh = Ah + 2 * MAT_U;                                      \
        __nv_bfloat16* Bl = Ah + 3 * MAT_U;                                      \
        _Pragma("unroll")                                                        \
        for (int p = 0; p < 4; p++) {                                            \
            int row = lr + p * 32;                                               \
            uint2 hi, lo;                                                        \
            cvt4(hi, lo, ra[p]);                                                 \
            *(uint2*)&Ah[row * PITCH + lc] = hi;                                 \
            *(uint2*)&Al[row * PITCH + lc] = lo;                                 \
            cvt4(hi, lo, rb[p]);                                                 \
            *(uint2*)&Bh[row * PITCH + lc] = hi;                                 \
            *(uint2*)&Bl[row * PITCH + lc] = lo;                                 \
        }                                                                        \
    } while (0)

    #define GEMM_COMPUTE(s) do {                                                 \
        uint32_t Ahi = sh0 + (s) * STAGE_U * 2;                                  \
        uint32_t Alo = Ahi + MAT_U * 2;                                          \
        uint32_t Bhi = Ahi + 2 * MAT_U * 2;                                      \
        uint32_t Blo = Ahi + 3 * MAT_U * 2;                                      \
        _Pragma("unroll")                                                        \
        for (int ks = 0; ks < 2; ks++) {                                         \
            uint32_t ah[2][4], al[2][4];                                         \
            _Pragma("unroll")                                                    \
            for (int mt = 0; mt < 2; mt++) {                                     \
                uint32_t off = (a_row + mt * 16) * 80 + a_col + ks * 32;         \
                ldsm_x4(ah[mt], Ahi + off);                                      \
                ldsm_x4(al[mt], Alo + off);                                      \
            }                                                                    \
            _Pragma("unroll")                                                    \
            for (int nt = 0; nt < 8; nt++) {                                     \
                uint32_t boff = (b_row + nt * 8) * 80 + b_col + ks * 32;         \
                uint32_t bh[2], bl[2];                                           \
                ldsm_x2(bh, Bhi + boff);                                         \
                ldsm_x2(bl, Blo + boff);                                         \
                _Pragma("unroll")                                                \
                for (int mt = 0; mt < 2; mt++) {                                 \
                    mma16816(acc[mt][nt], ah[mt], bh);                           \
                    mma16816(acc[mt][nt], ah[mt], bl);                           \
                    mma16816(acc[mt][nt], al[mt], bh);                           \
                }                                                                \
            }                                                                    \
        }                                                                        \
    } while (0)

    GEMM_LDG(0);
    GEMM_STS(0);
    __syncthreads();
    for (int c = 0; c < 32; c++) {
        if (c < 31) GEMM_LDG(c + 1);
        GEMM_COMPUTE(c & 1);
        __syncthreads();
        if (c < 31) { GEMM_STS((c + 1) & 1); __syncthreads(); }
    }

    const int er = lane >> 2, ec = (lane & 3) * 2;
    #pragma unroll
    for (int mt = 0; mt < 2; mt++)
        #pragma unroll
        for (int nt = 0; nt < 8; nt++) {
            int m = bm + wm + mt * 16 + er;
            int n = bn + wn + nt * 8 + ec;
            float2 v0 = make_float2(acc[mt][nt][0] * scale, acc[mt][nt][1] * scale);
            float2 v1 = make_float2(acc[mt][nt][2] * scale, acc[mt][nt][3] * scale);
            *(float2*)&Y[ymap(m,     n, mode)] = v0;
            *(float2*)&Y[ymap(m + 8, n, mode)] = v1;
        }
}

// ---- merged Q/K/V projection: grid z selects input/weight/output ----------
__global__ __launch_bounds__(256) void qkv_gemm(
    const float* __restrict__ q, const float* __restrict__ k, const float* __restrict__ v,
    const float* __restrict__ wq, const float* __restrict__ wk, const float* __restrict__ wv,
    float* __restrict__ yq, float* __restrict__ yk, float* __restrict__ yv)
{
    extern __shared__ __nv_bfloat16 sh[];
    const int z = blockIdx.z;
    const float* X = z == 0 ? q : z == 1 ? k : v;
    const float* W = z == 0 ? wq : z == 1 ? wk : wv;
    float*       Y = z == 0 ? yq : z == 1 ? yk : yv;
    gemm_core(X, W, Y, z == 0 ? 0.125f : 1.0f, 0,
              blockIdx.y * 128, blockIdx.x * 128, sh);
}

// ---- heterogeneous tail: W_O GEMM blocks interleaved with rescale blocks --
#define TAIL_GEMM 256
#define TAIL_RES  2048                 /* 65536 rows / 32 rows per block */
#define TAIL_GRID (TAIL_GEMM + TAIL_RES)

__global__ __launch_bounds__(256) void tail_kernel(
    const float* __restrict__ Ctx, const float* __restrict__ W_O,
    float* __restrict__ out, float* __restrict__ attn, const float* __restrict__ L)
{
    extern __shared__ __nv_bfloat16 sh[];
    const int bid = blockIdx.x;
    if (bid % 9 == 0) {                // 256 GEMM blocks: bid = 0,9,18,...,2295
        int g = bid / 9;
        gemm_core(Ctx, W_O, out, 1.0f, 1, (g >> 3) * 128, (g & 7) * 128, sh);
    } else if (attn) {                 // 2048 rescale blocks, 32 rows each
        int r = bid - bid / 9 - 1;     // 0..2047
        const int t = threadIdx.x;
        #pragma unroll 1
        for (int i = 0; i < 32; i++) {
            int row = r * 32 + i;
            float inv = 1.0f / L[row];
            float4* p = (float4*)(attn + (size_t)row * 2048);
            float4 v0 = p[t], v1 = p[t + 256];
            v0.x *= inv; v0.y *= inv; v0.z *= inv; v0.w *= inv;
            v1.x *= inv; v1.y *= inv; v1.z *= inv; v1.w *= inv;
            p[t] = v0; p[t + 256] = v1;
        }
    }
}

// ===========================================================================
// Tensor-core attention (R5-exact, measured 474us): 256 thr, 4q x 2k warps,
// 64-key chunks, in-loop split-bf16 conversion. Writes UNNORMALIZED attn,
// row sums to g_L, normalized context to g_C.
// ===========================================================================
#define AQHI 0
#define AQLO 18432
#define AKHI 36864
#define AKLO 46080
#define AVHI 55296
#define AVLO 64512
#define ALP  73728
#define AMSK 74752
#define AT_SMEM 75008
#define APB 144                       /* bytes per 72-bf16 row */

__global__ __launch_bounds__(256, 1) void attn_mma(
    const float* __restrict__ Qh, const float* __restrict__ Kh,
    const float* __restrict__ Vh, const int* __restrict__ mask,
    float* __restrict__ attn, float* __restrict__ Ctx, float* __restrict__ Lout)
{
    extern __shared__ char ash[];
    const uint32_t s0 = smem_u32(ash);
    float* Lpart = (float*)(ash + ALP);
    int*   Msk   = (int*)(ash + AMSK);

    const int t = threadIdx.x, warp = t >> 5, lane = t & 31;
    const int qw = warp >> 1, kw = warp & 1;
    const int q0 = blockIdx.x * 128, h = blockIdx.y, b = blockIdx.z;
    const int bh = b * H_ + h;
    const float* Qb = Qh + (size_t)bh * S_ * 64;
    const float* Kb = Kh + (size_t)bh * S_ * 64;
    const float* Vb = Vh + (size_t)bh * S_ * 64;

    Lpart[t] = 0.f;

    {
        const int lr = t >> 3, lc = (t & 7) * 8;
        #pragma unroll
        for (int p = 0; p < 4; p++) {
            int row = lr + 32 * p;
            const float* src = Qb + (size_t)(q0 + row) * 64 + lc;
            uint2 hi, lo;
            cvt4(hi, lo, *(const float4*)src);
            *(uint2*)(ash + AQHI + row * APB + lc * 2)     = hi;
            *(uint2*)(ash + AQLO + row * APB + lc * 2)     = lo;
            cvt4(hi, lo, *(const float4*)(src + 4));
            *(uint2*)(ash + AQHI + row * APB + lc * 2 + 8) = hi;
            *(uint2*)(ash + AQLO + row * APB + lc * 2 + 8) = lo;
        }
    }

    const int r8 = lane & 7, tl = lane >> 3;
    const int er = lane >> 2, ec = (lane & 3) * 2;
    const uint32_t a_roff = (uint32_t)((qw * 32 + (tl & 1) * 8 + r8) * APB + (tl >> 1) * 16);
    const uint32_t b_roff = (uint32_t)((kw * 32 + r8) * APB + (tl & 1) * 16);
    const uint32_t v_roff = (uint32_t)((kw * 32 + (tl & 1) * 8 + r8) * APB);

    float oacc[2][8][4];
    #pragma unroll
    for (int mt = 0; mt < 2; mt++)
        #pragma unroll
        for (int nt = 0; nt < 8; nt++)
            #pragma unroll
            for (int j = 0; j < 4; j++) oacc[mt][nt][j] = 0.f;

    for (int c = 0; c < 32; c++) {
        const int kb = c * 64;
        __syncthreads();

        {
            const int lr = t >> 3, lc = (t & 7) * 8;
            #pragma unroll
            for (int p = 0; p < 2; p++) {
                int row = lr + 32 * p;
                const float* sk = Kb + (size_t)(kb + row) * 64 + lc;
                const float* sv = Vb + (size_t)(kb + row) * 64 + lc;
                uint2 hi, lo;
                cvt4(hi, lo, *(const float4*)sk);
                *(uint2*)(ash + AKHI + row * APB + lc * 2)     = hi;
                *(uint2*)(ash + AKLO + row * APB + lc * 2)     = lo;
                cvt4(hi, lo, *(const float4*)(sk + 4));
                *(uint2*)(ash + AKHI + row * APB + lc * 2 + 8) = hi;
                *(uint2*)(ash + AKLO + row * APB + lc * 2 + 8) = lo;
                cvt4(hi, lo, *(const float4*)sv);
                *(uint2*)(ash + AVHI + row * APB + lc * 2)     = hi;
                *(uint2*)(ash + AVLO + row * APB + lc * 2)     = lo;
                cvt4(hi, lo, *(const float4*)(sv + 4));
                *(uint2*)(ash + AVHI + row * APB + lc * 2 + 8) = hi;
                *(uint2*)(ash + AVLO + row * APB + lc * 2 + 8) = lo;
            }
            if (t < 64) Msk[t] = mask[b * S_ + kb + t];
        }
        __syncthreads();

        float sc[2][4][4];
        #pragma unroll
        for (int mt = 0; mt < 2; mt++)
            #pragma unroll
            for (int nf = 0; nf < 4; nf++)
                #pragma unroll
                for (int j = 0; j < 4; j++) sc[mt][nf][j] = 0.f;

        #pragma unroll
        for (int ks = 0; ks < 4; ks++) {
            uint32_t qh_[2][4], ql_[2][4];
            #pragma unroll
            for (int mt = 0; mt < 2; mt++) {
                uint32_t off = a_roff + mt * 16 * APB + ks * 32;
                ldsm_x4(qh_[mt], s0 + AQHI + off);
                ldsm_x4(ql_[mt], s0 + AQLO + off);
            }
            #pragma unroll
            for (int nf = 0; nf < 4; nf++) {
                uint32_t boff = b_roff + nf * 8 * APB + ks * 32;
                uint32_t kh_[2], kl_[2];
                ldsm_x2(kh_, s0 + AKHI + boff);
                ldsm_x2(kl_, s0 + AKLO + boff);
                #pragma unroll
                for (int mt = 0; mt < 2; mt++) {
                    mma16816(sc[mt][nf], qh_[mt], kh_);
                    mma16816(sc[mt][nf], qh_[mt], kl_);
                    mma16816(sc[mt][nf], ql_[mt], kh_);
                }
            }
        }

        uint32_t phi[2][2][4], plo[2][2][4];
        #pragma unroll
        for (int mt = 0; mt < 2; mt++) {
            float rs0 = 0.f, rs1 = 0.f;
            #pragma unroll
            for (int nf = 0; nf < 4; nf++) {
                int col = kw * 32 + nf * 8 + ec;
                int m0 = Msk[col], m1 = Msk[col + 1];
                float p00 = m0 ? __expf(sc[mt][nf][0]) : 0.f;
                float p01 = m1 ? __expf(sc[mt][nf][1]) : 0.f;
                float p10 = m0 ? __expf(sc[mt][nf][2]) : 0.f;
                float p11 = m1 ? __expf(sc[mt][nf][3]) : 0.f;
                rs0 += p00 + p01; rs1 += p10 + p11;
                if (attn) {
                    int q = q0 + qw * 32 + mt * 16 + er;
                    size_t ro = ((size_t)bh * S_ + q) * S_ + kb + col;
                    *(float2*)&attn[ro]          = make_float2(p00, p01);
                    *(float2*)&attn[ro + 8 * S_] = make_float2(p10, p11);
                }
                int kf = nf >> 1, hf = (nf & 1) * 2;
                float h00 = bf_round(p00), h01 = bf_round(p01);
                float h10 = bf_round(p10), h11 = bf_round(p11);
                phi[mt][kf][hf]     = packbf(h00, h01);
                phi[mt][kf][hf + 1] = packbf(h10, h11);
                plo[mt][kf][hf]     = packbf(p00 - h00, p01 - h01);
                plo[mt][kf][hf + 1] = packbf(p10 - h10, p11 - h11);
            }
            rs0 += __shfl_xor_sync(0xffffffffu, rs0, 1);
            rs0 += __shfl_xor_sync(0xffffffffu, rs0, 2);
            rs1 += __shfl_xor_sync(0xffffffffu, rs1, 1);
            rs1 += __shfl_xor_sync(0xffffffffu, rs1, 2);
            if ((lane & 3) == 0) {
                int q = qw * 32 + mt * 16 + er;
                Lpart[kw * 128 + q]     += rs0;
                Lpart[kw * 128 + q + 8] += rs1;
            }
        }

        #pragma unroll
        for (int kf = 0; kf < 2; kf++) {
            #pragma unroll
            for (int nf2 = 0; nf2 < 8; nf2++) {
                uint32_t voff = v_roff + kf * 16 * APB + nf2 * 16;
                uint32_t vh_[2], vl_[2];
                ldsm_x2t(vh_, s0 + AVHI + voff);
                ldsm_x2t(vl_, s0 + AVLO + voff);
                #pragma unroll
                for (int mt = 0; mt < 2; mt++) {
                    mma16816(oacc[mt][nf2], phi[mt][kf], vh_);
                    mma16816(oacc[mt][nf2], phi[mt][kf], vl_);
                    mma16816(oacc[mt][nf2], plo[mt][kf], vh_);
                }
            }
        }
    }

    __syncthreads();
    float* Ored = (float*)(ash + AKHI);
    if (kw == 1) {
        #pragma unroll
        for (int mt = 0; mt < 2; mt++)
            #pragma unroll
            for (int nf2 = 0; nf2 < 8; nf2++) {
                int q = qw * 32 + mt * 16 + er, d = nf2 * 8 + ec;
                *(float2*)&Ored[q * 68 + d]       = make_float2(oacc[mt][nf2][0], oacc[mt][nf2][1]);
                *(float2*)&Ored[(q + 8) * 68 + d] = make_float2(oacc[mt][nf2][2], oacc[mt][nf2][3]);
            }
    }
    __syncthreads();
    if (kw == 0) {
        #pragma unroll
        for (int mt = 0; mt < 2; mt++) {
            int qA = qw * 32 + mt * 16 + er;
            float invA = 1.f / (Lpart[qA] + Lpart[128 + qA]);
            float invB = 1.f / (Lpart[qA + 8] + Lpart[128 + qA + 8]);
            #pragma unroll
            for (int nf2 = 0; nf2 < 8; nf2++) {
                int d = nf2 * 8 + ec;
                float2 oA = *(float2*)&Ored[qA * 68 + d];
                float2 oB = *(float2*)&Ored[(qA + 8) * 68 + d];
                oA.x = (oA.x + oacc[mt][nf2][0]) * invA;
                oA.y = (oA.y + oacc[mt][nf2][1]) * invA;
                oB.x = (oB.x + oacc[mt][nf2][2]) * invB;
                oB.y = (oB.y + oacc[mt][nf2][3]) * invB;
                size_t oo = ((size_t)b * S_ + q0 + qA) * D_ + h * 64 + d;
                *(float2*)&Ctx[oo]          = oA;
                *(float2*)&Ctx[oo + 8 * D_] = oB;
            }
        }
    }
    if (t < 128) Lout[(size_t)bh * S_ + q0 + t] = Lpart[t] + Lpart[128 + t];
}

// ===========================================================================
extern "C" void kernel_launch(void* const* d_in, const int* in_sizes, int n_in,
                              void* d_out, int out_size)
{
    const float* query = (const float*)d_in[0];
    const float* key   = (const float*)d_in[1];
    const float* value = (const float*)d_in[2];
    const int*   mask  = (const int*)d_in[3];
    const float* W_Q   = (const float*)d_in[4];
    const float* W_K   = (const float*)d_in[5];
    const float* W_V   = (const float*)d_in[6];
    const float* W_O   = (const float*)d_in[7];

    float* out = (float*)d_out;
    bool hasAttn = (out_size >= OUT_ELEMS + ATT_ELEMS);
    float* attn = hasAttn ? (out + OUT_ELEMS) : nullptr;

    float *gq, *gk, *gv, *gc, *gl;
    cudaGetSymbolAddress((void**)&gq, g_Q);
    cudaGetSymbolAddress((void**)&gk, g_K);
    cudaGetSymbolAddress((void**)&gv, g_V);
    cudaGetSymbolAddress((void**)&gc, g_C);
    cudaGetSymbolAddress((void**)&gl, g_L);

    cudaFuncSetAttribute((const void*)attn_mma,
                         cudaFuncAttributeMaxDynamicSharedMemorySize, AT_SMEM);
    cudaFuncSetAttribute((const void*)qkv_gemm,
                         cudaFuncAttributeMaxDynamicSharedMemorySize, GT_SMEM);
    cudaFuncSetAttribute((const void*)tail_kernel,
                         cudaFuncAttributeMaxDynamicSharedMemorySize, GT_SMEM);

    qkv_gemm<<<dim3(8, 32, 3), 256, GT_SMEM>>>(query, key, value,
                                               W_Q, W_K, W_V, gq, gk, gv);
    attn_mma<<<dim3(16, 16, 2), 256, AT_SMEM>>>(gq, gk, gv, mask, attn, gc, gl);
    tail_kernel<<<TAIL_GRID, 256, GT_SMEM>>>(gc, W_O, out, attn, gl);
}

// round 10
// speedup vs baseline: 1.1463x; 1.1463x over previous
#include <cuda_runtime.h>
#include <cuda_bf16.h>
#include <cstdint>

#define B_ 2
#define S_ 2048
#define D_ 1024
#define H_ 16
#define DK_ 64
#define OUT_ELEMS (B_*S_*D_)           /* 4194304  */
#define ATT_ELEMS (B_*H_*S_*S_)        /* 134217728 */

// ---------------- scratch (device globals; no allocation allowed) ----------
__device__ float g_Q[B_*H_*S_*DK_];    // [b][h][s][d], pre-scaled by 1/8
__device__ float g_K[B_*H_*S_*DK_];
__device__ float g_V[B_*H_*S_*DK_];
__device__ float g_C[B_*S_*D_];        // context, token-major
__device__ float g_L[B_*H_*S_];        // softmax row sums

__device__ __forceinline__ uint32_t smem_u32(const void* p) {
    uint32_t a;
    asm("{ .reg .u64 t; cvta.to.shared.u64 t, %1; cvt.u32.u64 %0, t; }" : "=r"(a) : "l"(p));
    return a;
}

// ---------------- mma.sync primitives (baseline PTX, no 'a' features) ------
__device__ __forceinline__ void ldsm_x4(uint32_t (&r)[4], uint32_t addr) {
    asm volatile("ldmatrix.sync.aligned.m8n8.x4.shared.b16 {%0,%1,%2,%3}, [%4];"
        : "=r"(r[0]), "=r"(r[1]), "=r"(r[2]), "=r"(r[3]) : "r"(addr));
}
__device__ __forceinline__ void ldsm_x2(uint32_t (&r)[2], uint32_t addr) {
    asm volatile("ldmatrix.sync.aligned.m8n8.x2.shared.b16 {%0,%1}, [%2];"
        : "=r"(r[0]), "=r"(r[1]) : "r"(addr));
}
__device__ __forceinline__ void ldsm_x2t(uint32_t (&r)[2], uint32_t addr) {
    asm volatile("ldmatrix.sync.aligned.m8n8.x2.trans.shared.b16 {%0,%1}, [%2];"
        : "=r"(r[0]), "=r"(r[1]) : "r"(addr));
}
__device__ __forceinline__ void mma16816(float (&c)[4], const uint32_t (&a)[4],
                                         const uint32_t (&b)[2]) {
    asm volatile("mma.sync.aligned.m16n8k16.row.col.f32.bf16.bf16.f32 "
        "{%0,%1,%2,%3}, {%4,%5,%6,%7}, {%8,%9}, {%0,%1,%2,%3};"
        : "+f"(c[0]), "+f"(c[1]), "+f"(c[2]), "+f"(c[3])
        : "r"(a[0]), "r"(a[1]), "r"(a[2]), "r"(a[3]), "r"(b[0]), "r"(b[1]));
}
__device__ __forceinline__ uint32_t packbf(float lo, float hi) {
    uint32_t r;
    asm("cvt.rn.bf16x2.f32 %0, %1, %2;" : "=r"(r) : "f"(hi), "f"(lo));
    return r;
}
__device__ __forceinline__ float bf_round(float x) {
    return __bfloat162float(__float2bfloat16(x));
}
__device__ __forceinline__ void cvt4(uint2 &hi, uint2 &lo, float4 vv) {
    float v0 = vv.x, v1 = vv.y, v2 = vv.z, v3 = vv.w;
    __nv_bfloat16 h0 = __float2bfloat16(v0), h1 = __float2bfloat16(v1);
    __nv_bfloat16 h2 = __float2bfloat16(v2), h3 = __float2bfloat16(v3);
    __nv_bfloat162 hh0(h0, h1), hh1(h2, h3);
    __nv_bfloat162 ll0(__float2bfloat16(v0 - __bfloat162float(h0)),
                       __float2bfloat16(v1 - __bfloat162float(h1)));
    __nv_bfloat162 ll1(__float2bfloat16(v2 - __bfloat162float(h2)),
                       __float2bfloat16(v3 - __bfloat162float(h3)));
    hi = make_uint2(*(uint32_t*)&hh0, *(uint32_t*)&hh1);
    lo = make_uint2(*(uint32_t*)&ll0, *(uint32_t*)&ll1);
}

// ===========================================================================
// Split-bf16 tensor-core GEMM core (inlined by callers).
// ===========================================================================
#define PITCH 40
#define MAT_U (128*PITCH)
#define STAGE_U (4*MAT_U)
#define GT_SMEM (2*STAGE_U*2)

__device__ __forceinline__ size_t ymap(int m, int n, int mode) {
    if (mode == 0)
        return (((size_t)((m >> 11) * 16 + (n >> 6))) * 2048 + (m & 2047)) * 64 + (n & 63);
    return (size_t)m * 1024 + n;
}

__device__ __forceinline__ void gemm_core(
    const float* __restrict__ X, const float* __restrict__ W,
    float* __restrict__ Y, float scale, int mode, int bm, int bn,
    __nv_bfloat16* sh)
{
    const uint32_t sh0 = smem_u32(sh);
    const int t = threadIdx.x;
    const int warp = t >> 5, lane = t & 31;
    const int wm = (warp >> 1) * 32;
    const int wn = (warp & 1) * 64;
    const int lr = t >> 3, lc = (t & 7) * 4;

    float4 ra[4], rb[4];
    float acc[2][8][4];
    #pragma unroll
    for (int mt = 0; mt < 2; mt++)
        #pragma unroll
        for (int nt = 0; nt < 8; nt++)
            #pragma unroll
            for (int j = 0; j < 4; j++) acc[mt][nt][j] = 0.f;

    const int r8 = lane & 7, tl = lane >> 3;
    const uint32_t a_row = (uint32_t)(wm + (tl & 1) * 8 + r8);
    const uint32_t a_col = (uint32_t)((tl >> 1) * 16);
    const uint32_t b_row = (uint32_t)(wn + r8);
    const uint32_t b_col = (uint32_t)((tl & 1) * 16);

    #define GEMM_LDG(c) do {                                                     \
        const float* xp = X + (size_t)(bm + lr) * 1024 + (c) * 32 + lc;          \
        const float* wp = W + (size_t)(bn + lr) * 1024 + (c) * 32 + lc;          \
        _Pragma("unroll")                                                        \
        for (int p = 0; p < 4; p++) {                                            \
            ra[p] = *(const float4*)(xp + (size_t)p * 32 * 1024);                \
            rb[p] = *(const float4*)(wp + (size_t)p * 32 * 1024);                \
        }                                                                        \
    } while (0)

    #define GEMM_STS(s) do {                                                     \
        __nv_bfloat16* Ah = sh + (s) * STAGE_U;                                  \
        __nv_bfloat16* Al = Ah + MAT_U;                                          \
        __nv_bfloat16* Bh = Ah + 2 * MAT_U;                                      \
        __nv_bfloat16* Bl = Ah + 3 * MAT_U;                                      \
        _Pragma("unroll")                                                        \
        for (int p = 0; p < 4; p++) {                                            \
            int row = lr + p * 32;                                               \
            uint2 hi, lo;                                                        \
            cvt4(hi, lo, ra[p]);                                                 \
            *(uint2*)&Ah[row * PITCH + lc] = hi;                                 \
            *(uint2*)&Al[row * PITCH + lc] = lo;                                 \
            cvt4(hi, lo, rb[p]);                                                 \
            *(uint2*)&Bh[row * PITCH + lc] = hi;                                 \
            *(uint2*)&Bl[row * PITCH + lc] = lo;                                 \
        }                                                                        \
    } while (0)

    #define GEMM_COMPUTE(s) do {                                                 \
        uint32_t Ahi = sh0 + (s) * STAGE_U * 2;                                  \
        uint32_t Alo = Ahi + MAT_U * 2;                                          \
        uint32_t Bhi = Ahi + 2 * MAT_U * 2;                                      \
        uint32_t Blo = Ahi + 3 * MAT_U * 2;                                      \
        _Pragma("unroll")                                                        \
        for (int ks = 0; ks < 2; ks++) {                                         \
            uint32_t ah[2][4], al[2][4];                                         \
            _Pragma("unroll")                                                    \
            for (int mt = 0; mt < 2; mt++) {                                     \
                uint32_t off = (a_row + mt * 16) * 80 + a_col + ks * 32;         \
                ldsm_x4(ah[mt], Ahi + off);                                      \
                ldsm_x4(al[mt], Alo + off);                                      \
            }                                                                    \
            _Pragma("unroll")                                                    \
            for (int nt = 0; nt < 8; nt++) {                                     \
                uint32_t boff = (b_row + nt * 8) * 80 + b_col + ks * 32;         \
                uint32_t bh[2], bl[2];                                           \
                ldsm_x2(bh, Bhi + boff);                                         \
                ldsm_x2(bl, Blo + boff);                                         \
                _Pragma("unroll")                                                \
                for (int mt = 0; mt < 2; mt++) {                                 \
                    mma16816(acc[mt][nt], ah[mt], bh);                           \
                    mma16816(acc[mt][nt], ah[mt], bl);                           \
                    mma16816(acc[mt][nt], al[mt], bh);                           \
                }                                                                \
            }                                                                    \
        }                                                                        \
    } while (0)

    GEMM_LDG(0);
    GEMM_STS(0);
    __syncthreads();
    for (int c = 0; c < 32; c++) {
        if (c < 31) GEMM_LDG(c + 1);
        GEMM_COMPUTE(c & 1);
        __syncthreads();
        if (c < 31) { GEMM_STS((c + 1) & 1); __syncthreads(); }
    }

    const int er = lane >> 2, ec = (lane & 3) * 2;
    #pragma unroll
    for (int mt = 0; mt < 2; mt++)
        #pragma unroll
        for (int nt = 0; nt < 8; nt++) {
            int m = bm + wm + mt * 16 + er;
            int n = bn + wn + nt * 8 + ec;
            float2 v0 = make_float2(acc[mt][nt][0] * scale, acc[mt][nt][1] * scale);
            float2 v1 = make_float2(acc[mt][nt][2] * scale, acc[mt][nt][3] * scale);
            *(float2*)&Y[ymap(m,     n, mode)] = v0;
            *(float2*)&Y[ymap(m + 8, n, mode)] = v1;
        }
}

// ---- merged Q/K/V projection: grid z selects input/weight/output ----------
__global__ __launch_bounds__(256) void qkv_gemm(
    const float* __restrict__ q, const float* __restrict__ k, const float* __restrict__ v,
    const float* __restrict__ wq, const float* __restrict__ wk, const float* __restrict__ wv,
    float* __restrict__ yq, float* __restrict__ yk, float* __restrict__ yv)
{
    extern __shared__ __nv_bfloat16 sh[];
    const int z = blockIdx.z;
    const float* X = z == 0 ? q : z == 1 ? k : v;
    const float* W = z == 0 ? wq : z == 1 ? wk : wv;
    float*       Y = z == 0 ? yq : z == 1 ? yk : yv;
    gemm_core(X, W, Y, z == 0 ? 0.125f : 1.0f, 0,
              blockIdx.y * 128, blockIdx.x * 128, sh);
}

// ---- heterogeneous tail: W_O GEMM blocks interleaved with rescale blocks --
// Rescale blocks restructured for MLP: 4 rows per iteration, 8 independent
// float4 loads in flight per thread.
#define TAIL_GEMM 256
#define TAIL_RES  2048                 /* 65536 rows / 32 rows per block */
#define TAIL_GRID (TAIL_GEMM + TAIL_RES)

__global__ __launch_bounds__(256) void tail_kernel(
    const float* __restrict__ Ctx, const float* __restrict__ W_O,
    float* __restrict__ out, float* __restrict__ attn, const float* __restrict__ L)
{
    extern __shared__ __nv_bfloat16 sh[];
    const int bid = blockIdx.x;
    if (bid % 9 == 0) {                // 256 GEMM blocks: bid = 0,9,18,...,2295
        int g = bid / 9;
        gemm_core(Ctx, W_O, out, 1.0f, 1, (g >> 3) * 128, (g & 7) * 128, sh);
    } else if (attn) {                 // 2048 rescale blocks, 32 rows each
        int r = bid - bid / 9 - 1;     // 0..2047
        const int t = threadIdx.x;
        const int row0 = r * 32;
        float4* base = (float4*)(attn + (size_t)row0 * 2048);
        #pragma unroll 1
        for (int g = 0; g < 8; g++) {
            float inv0 = 1.0f / L[row0 + g*4 + 0];
            float inv1 = 1.0f / L[row0 + g*4 + 1];
            float inv2 = 1.0f / L[row0 + g*4 + 2];
            float inv3 = 1.0f / L[row0 + g*4 + 3];
            float4* p0 = base + (size_t)(g*4 + 0) * 512;
            float4* p1 = base + (size_t)(g*4 + 1) * 512;
            float4* p2 = base + (size_t)(g*4 + 2) * 512;
            float4* p3 = base + (size_t)(g*4 + 3) * 512;
            float4 a0 = p0[t], b0 = p0[t + 256];
            float4 a1 = p1[t], b1 = p1[t + 256];
            float4 a2 = p2[t], b2 = p2[t + 256];
            float4 a3 = p3[t], b3 = p3[t + 256];
            a0.x *= inv0; a0.y *= inv0; a0.z *= inv0; a0.w *= inv0;
            b0.x *= inv0; b0.y *= inv0; b0.z *= inv0; b0.w *= inv0;
            a1.x *= inv1; a1.y *= inv1; a1.z *= inv1; a1.w *= inv1;
            b1.x *= inv1; b1.y *= inv1; b1.z *= inv1; b1.w *= inv1;
            a2.x *= inv2; a2.y *= inv2; a2.z *= inv2; a2.w *= inv2;
            b2.x *= inv2; b2.y *= inv2; b2.z *= inv2; b2.w *= inv2;
            a3.x *= inv3; a3.y *= inv3; a3.z *= inv3; a3.w *= inv3;
            b3.x *= inv3; b3.y *= inv3; b3.z *= inv3; b3.w *= inv3;
            p0[t] = a0; p0[t + 256] = b0;
            p1[t] = a1; p1[t + 256] = b1;
            p2[t] = a2; p2[t + 256] = b2;
            p3[t] = a3; p3[t + 256] = b3;
        }
    }
}

// ===========================================================================
// Tensor-core attention (R5-exact, measured 474us): 256 thr, 4q x 2k warps,
// 64-key chunks, in-loop split-bf16 conversion. Writes UNNORMALIZED attn,
// row sums to g_L, normalized context to g_C.
// ===========================================================================
#define AQHI 0
#define AQLO 18432
#define AKHI 36864
#define AKLO 46080
#define AVHI 55296
#define AVLO 64512
#define ALP  73728
#define AMSK 74752
#define AT_SMEM 75008
#define APB 144                       /* bytes per 72-bf16 row */

__global__ __launch_bounds__(256, 1) void attn_mma(
    const float* __restrict__ Qh, const float* __restrict__ Kh,
    const float* __restrict__ Vh, const int* __restrict__ mask,
    float* __restrict__ attn, float* __restrict__ Ctx, float* __restrict__ Lout)
{
    extern __shared__ char ash[];
    const uint32_t s0 = smem_u32(ash);
    float* Lpart = (float*)(ash + ALP);
    int*   Msk   = (int*)(ash + AMSK);

    const int t = threadIdx.x, warp = t >> 5, lane = t & 31;
    const int qw = warp >> 1, kw = warp & 1;
    const int q0 = blockIdx.x * 128, h = blockIdx.y, b = blockIdx.z;
    const int bh = b * H_ + h;
    const float* Qb = Qh + (size_t)bh * S_ * 64;
    const float* Kb = Kh + (size_t)bh * S_ * 64;
    const float* Vb = Vh + (size_t)bh * S_ * 64;

    Lpart[t] = 0.f;

    {
        const int lr = t >> 3, lc = (t & 7) * 8;
        #pragma unroll
        for (int p = 0; p < 4; p++) {
            int row = lr + 32 * p;
            const float* src = Qb + (size_t)(q0 + row) * 64 + lc;
            uint2 hi, lo;
            cvt4(hi, lo, *(const float4*)src);
            *(uint2*)(ash + AQHI + row * APB + lc * 2)     = hi;
            *(uint2*)(ash + AQLO + row * APB + lc * 2)     = lo;
            cvt4(hi, lo, *(const float4*)(src + 4));
            *(uint2*)(ash + AQHI + row * APB + lc * 2 + 8) = hi;
            *(uint2*)(ash + AQLO + row * APB + lc * 2 + 8) = lo;
        }
    }

    const int r8 = lane & 7, tl = lane >> 3;
    const int er = lane >> 2, ec = (lane & 3) * 2;
    const uint32_t a_roff = (uint32_t)((qw * 32 + (tl & 1) * 8 + r8) * APB + (tl >> 1) * 16);
    const uint32_t b_roff = (uint32_t)((kw * 32 + r8) * APB + (tl & 1) * 16);
    const uint32_t v_roff = (uint32_t)((kw * 32 + (tl & 1) * 8 + r8) * APB);

    float oacc[2][8][4];
    #pragma unroll
    for (int mt = 0; mt < 2; mt++)
        #pragma unroll
        for (int nt = 0; nt < 8; nt++)
            #pragma unroll
            for (int j = 0; j < 4; j++) oacc[mt][nt][j] = 0.f;

    for (int c = 0; c < 32; c++) {
        const int kb = c * 64;
        __syncthreads();

        {
            const int lr = t >> 3, lc = (t & 7) * 8;
            #pragma unroll
            for (int p = 0; p < 2; p++) {
                int row = lr + 32 * p;
                const float* sk = Kb + (size_t)(kb + row) * 64 + lc;
                const float* sv = Vb + (size_t)(kb + row) * 64 + lc;
                uint2 hi, lo;
                cvt4(hi, lo, *(const float4*)sk);
                *(uint2*)(ash + AKHI + row * APB + lc * 2)     = hi;
                *(uint2*)(ash + AKLO + row * APB + lc * 2)     = lo;
                cvt4(hi, lo, *(const float4*)(sk + 4));
                *(uint2*)(ash + AKHI + row * APB + lc * 2 + 8) = hi;
                *(uint2*)(ash + AKLO + row * APB + lc * 2 + 8) = lo;
                cvt4(hi, lo, *(const float4*)sv);
                *(uint2*)(ash + AVHI + row * APB + lc * 2)     = hi;
                *(uint2*)(ash + AVLO + row * APB + lc * 2)     = lo;
                cvt4(hi, lo, *(const float4*)(sv + 4));
                *(uint2*)(ash + AVHI + row * APB + lc * 2 + 8) = hi;
                *(uint2*)(ash + AVLO + row * APB + lc * 2 + 8) = lo;
            }
            if (t < 64) Msk[t] = mask[b * S_ + kb + t];
        }
        __syncthreads();

        float sc[2][4][4];
        #pragma unroll
        for (int mt = 0; mt < 2; mt++)
            #pragma unroll
            for (int nf = 0; nf < 4; nf++)
                #pragma unroll
                for (int j = 0; j < 4; j++) sc[mt][nf][j] = 0.f;

        #pragma unroll
        for (int ks = 0; ks < 4; ks++) {
            uint32_t qh_[2][4], ql_[2][4];
            #pragma unroll
            for (int mt = 0; mt < 2; mt++) {
                uint32_t off = a_roff + mt * 16 * APB + ks * 32;
                ldsm_x4(qh_[mt], s0 + AQHI + off);
                ldsm_x4(ql_[mt], s0 + AQLO + off);
            }
            #pragma unroll
            for (int nf = 0; nf < 4; nf++) {
                uint32_t boff = b_roff + nf * 8 * APB + ks * 32;
                uint32_t kh_[2], kl_[2];
                ldsm_x2(kh_, s0 + AKHI + boff);
                ldsm_x2(kl_, s0 + AKLO + boff);
                #pragma unroll
                for (int mt = 0; mt < 2; mt++) {
                    mma16816(sc[mt][nf], qh_[mt], kh_);
                    mma16816(sc[mt][nf], qh_[mt], kl_);
                    mma16816(sc[mt][nf], ql_[mt], kh_);
                }
            }
        }

        uint32_t phi[2][2][4], plo[2][2][4];
        #pragma unroll
        for (int mt = 0; mt < 2; mt++) {
            float rs0 = 0.f, rs1 = 0.f;
            #pragma unroll
            for (int nf = 0; nf < 4; nf++) {
                int col = kw * 32 + nf * 8 + ec;
                int m0 = Msk[col], m1 = Msk[col + 1];
                float p00 = m0 ? __expf(sc[mt][nf][0]) : 0.f;
                float p01 = m1 ? __expf(sc[mt][nf][1]) : 0.f;
                float p10 = m0 ? __expf(sc[mt][nf][2]) : 0.f;
                float p11 = m1 ? __expf(sc[mt][nf][3]) : 0.f;
                rs0 += p00 + p01; rs1 += p10 + p11;
                if (attn) {
                    int q = q0 + qw * 32 + mt * 16 + er;
                    size_t ro = ((size_t)bh * S_ + q) * S_ + kb + col;
                    *(float2*)&attn[ro]          = make_float2(p00, p01);
                    *(float2*)&attn[ro + 8 * S_] = make_float2(p10, p11);
                }
                int kf = nf >> 1, hf = (nf & 1) * 2;
                float h00 = bf_round(p00), h01 = bf_round(p01);
                float h10 = bf_round(p10), h11 = bf_round(p11);
                phi[mt][kf][hf]     = packbf(h00, h01);
                phi[mt][kf][hf + 1] = packbf(h10, h11);
                plo[mt][kf][hf]     = packbf(p00 - h00, p01 - h01);
                plo[mt][kf][hf + 1] = packbf(p10 - h10, p11 - h11);
            }
            rs0 += __shfl_xor_sync(0xffffffffu, rs0, 1);
            rs0 += __shfl_xor_sync(0xffffffffu, rs0, 2);
            rs1 += __shfl_xor_sync(0xffffffffu, rs1, 1);
            rs1 += __shfl_xor_sync(0xffffffffu, rs1, 2);
            if ((lane & 3) == 0) {
                int q = qw * 32 + mt * 16 + er;
                Lpart[kw * 128 + q]     += rs0;
                Lpart[kw * 128 + q + 8] += rs1;
            }
        }

        #pragma unroll
        for (int kf = 0; kf < 2; kf++) {
            #pragma unroll
            for (int nf2 = 0; nf2 < 8; nf2++) {
                uint32_t voff = v_roff + kf * 16 * APB + nf2 * 16;
                uint32_t vh_[2], vl_[2];
                ldsm_x2t(vh_, s0 + AVHI + voff);
                ldsm_x2t(vl_, s0 + AVLO + voff);
                #pragma unroll
                for (int mt = 0; mt < 2; mt++) {
                    mma16816(oacc[mt][nf2], phi[mt][kf], vh_);
                    mma16816(oacc[mt][nf2], phi[mt][kf], vl_);
                    mma16816(oacc[mt][nf2], plo[mt][kf], vh_);
                }
            }
        }
    }

    __syncthreads();
    float* Ored = (float*)(ash + AKHI);
    if (kw == 1) {
        #pragma unroll
        for (int mt = 0; mt < 2; mt++)
            #pragma unroll
            for (int nf2 = 0; nf2 < 8; nf2++) {
                int q = qw * 32 + mt * 16 + er, d = nf2 * 8 + ec;
                *(float2*)&Ored[q * 68 + d]       = make_float2(oacc[mt][nf2][0], oacc[mt][nf2][1]);
                *(float2*)&Ored[(q + 8) * 68 + d] = make_float2(oacc[mt][nf2][2], oacc[mt][nf2][3]);
            }
    }
    __syncthreads();
    if (kw == 0) {
        #pragma unroll
        for (int mt = 0; mt < 2; mt++) {
            int qA = qw * 32 + mt * 16 + er;
            float invA = 1.f / (Lpart[qA] + Lpart[128 + qA]);
            float invB = 1.f / (Lpart[qA + 8] + Lpart[128 + qA + 8]);
            #pragma unroll
            for (int nf2 = 0; nf2 < 8; nf2++) {
                int d = nf2 * 8 + ec;
                float2 oA = *(float2*)&Ored[qA * 68 + d];
                float2 oB = *(float2*)&Ored[(qA + 8) * 68 + d];
                oA.x = (oA.x + oacc[mt][nf2][0]) * invA;
                oA.y = (oA.y + oacc[mt][nf2][1]) * invA;
                oB.x = (oB.x + oacc[mt][nf2][2]) * invB;
                oB.y = (oB.y + oacc[mt][nf2][3]) * invB;
                size_t oo = ((size_t)b * S_ + q0 + qA) * D_ + h * 64 + d;
                *(float2*)&Ctx[oo]          = oA;
                *(float2*)&Ctx[oo + 8 * D_] = oB;
            }
        }
    }
    if (t < 128) Lout[(size_t)bh * S_ + q0 + t] = Lpart[t] + Lpart[128 + t];
}

// ===========================================================================
extern "C" void kernel_launch(void* const* d_in, const int* in_sizes, int n_in,
                              void* d_out, int out_size)
{
    const float* query = (const float*)d_in[0];
    const float* key   = (const float*)d_in[1];
    const float* value = (const float*)d_in[2];
    const int*   mask  = (const int*)d_in[3];
    const float* W_Q   = (const float*)d_in[4];
    const float* W_K   = (const float*)d_in[5];
    const float* W_V   = (const float*)d_in[6];
    const float* W_O   = (const float*)d_in[7];

    float* out = (float*)d_out;
    bool hasAttn = (out_size >= OUT_ELEMS + ATT_ELEMS);
    float* attn = hasAttn ? (out + OUT_ELEMS) : nullptr;

    float *gq, *gk, *gv, *gc, *gl;
    cudaGetSymbolAddress((void**)&gq, g_Q);
    cudaGetSymbolAddress((void**)&gk, g_K);
    cudaGetSymbolAddress((void**)&gv, g_V);
    cudaGetSymbolAddress((void**)&gc, g_C);
    cudaGetSymbolAddress((void**)&gl, g_L);

    cudaFuncSetAttribute((const void*)attn_mma,
                         cudaFuncAttributeMaxDynamicSharedMemorySize, AT_SMEM);
    cudaFuncSetAttribute((const void*)qkv_gemm,
                         cudaFuncAttributeMaxDynamicSharedMemorySize, GT_SMEM);
    cudaFuncSetAttribute((const void*)tail_kernel,
                         cudaFuncAttributeMaxDynamicSharedMemorySize, GT_SMEM);

    qkv_gemm<<<dim3(8, 32, 3), 256, GT_SMEM>>>(query, key, value,
                                               W_Q, W_K, W_V, gq, gk, gv);
    attn_mma<<<dim3(16, 16, 2), 256, AT_SMEM>>>(gq, gk, gv, mask, attn, gc, gl);
    tail_kernel<<<TAIL_GRID, 256, GT_SMEM>>>(gc, W_O, out, attn, gl);
}

// round 11
// speedup vs baseline: 1.1891x; 1.0373x over previous
#include <cuda_runtime.h>
#include <cuda_bf16.h>
#include <cstdint>

#define B_ 2
#define S_ 2048
#define D_ 1024
#define H_ 16
#define DK_ 64
#define OUT_ELEMS (B_*S_*D_)           /* 4194304  */
#define ATT_ELEMS (B_*H_*S_*S_)        /* 134217728 */

// ---------------- scratch (device globals; no allocation allowed) ----------
__device__ float g_Q[B_*H_*S_*DK_];    // [b][h][s][d], pre-scaled by 1/8
__device__ float g_K[B_*H_*S_*DK_];
__device__ float g_V[B_*H_*S_*DK_];
__device__ float g_C[B_*S_*D_];        // context, token-major
__device__ float g_L[B_*H_*S_];        // softmax row sums

__device__ __forceinline__ uint32_t smem_u32(const void* p) {
    uint32_t a;
    asm("{ .reg .u64 t; cvta.to.shared.u64 t, %1; cvt.u32.u64 %0, t; }" : "=r"(a) : "l"(p));
    return a;
}

// ---------------- mma.sync primitives (baseline PTX, no 'a' features) ------
__device__ __forceinline__ void ldsm_x4(uint32_t (&r)[4], uint32_t addr) {
    asm volatile("ldmatrix.sync.aligned.m8n8.x4.shared.b16 {%0,%1,%2,%3}, [%4];"
        : "=r"(r[0]), "=r"(r[1]), "=r"(r[2]), "=r"(r[3]) : "r"(addr));
}
__device__ __forceinline__ void ldsm_x2(uint32_t (&r)[2], uint32_t addr) {
    asm volatile("ldmatrix.sync.aligned.m8n8.x2.shared.b16 {%0,%1}, [%2];"
        : "=r"(r[0]), "=r"(r[1]) : "r"(addr));
}
__device__ __forceinline__ void ldsm_x2t(uint32_t (&r)[2], uint32_t addr) {
    asm volatile("ldmatrix.sync.aligned.m8n8.x2.trans.shared.b16 {%0,%1}, [%2];"
        : "=r"(r[0]), "=r"(r[1]) : "r"(addr));
}
__device__ __forceinline__ void mma16816(float (&c)[4], const uint32_t (&a)[4],
                                         const uint32_t (&b)[2]) {
    asm volatile("mma.sync.aligned.m16n8k16.row.col.f32.bf16.bf16.f32 "
        "{%0,%1,%2,%3}, {%4,%5,%6,%7}, {%8,%9}, {%0,%1,%2,%3};"
        : "+f"(c[0]), "+f"(c[1]), "+f"(c[2]), "+f"(c[3])
        : "r"(a[0]), "r"(a[1]), "r"(a[2]), "r"(a[3]), "r"(b[0]), "r"(b[1]));
}
__device__ __forceinline__ uint32_t packbf(float lo, float hi) {
    uint32_t r;
    asm("cvt.rn.bf16x2.f32 %0, %1, %2;" : "=r"(r) : "f"(hi), "f"(lo));
    return r;
}
__device__ __forceinline__ float bf_round(float x) {
    return __bfloat162float(__float2bfloat16(x));
}
__device__ __forceinline__ void cvt4(uint2 &hi, uint2 &lo, float4 vv) {
    float v0 = vv.x, v1 = vv.y, v2 = vv.z, v3 = vv.w;
    __nv_bfloat16 h0 = __float2bfloat16(v0), h1 = __float2bfloat16(v1);
    __nv_bfloat16 h2 = __float2bfloat16(v2), h3 = __float2bfloat16(v3);
    __nv_bfloat162 hh0(h0, h1), hh1(h2, h3);
    __nv_bfloat162 ll0(__float2bfloat16(v0 - __bfloat162float(h0)),
                       __float2bfloat16(v1 - __bfloat162float(h1)));
    __nv_bfloat162 ll1(__float2bfloat16(v2 - __bfloat162float(h2)),
                       __float2bfloat16(v3 - __bfloat162float(h3)));
    hi = make_uint2(*(uint32_t*)&hh0, *(uint32_t*)&hh1);
    lo = make_uint2(*(uint32_t*)&ll0, *(uint32_t*)&ll1);
}

// ===========================================================================
// Split-bf16 tensor-core GEMM core (inlined by callers).
// ===========================================================================
#define PITCH 40
#define MAT_U (128*PITCH)
#define STAGE_U (4*MAT_U)
#define GT_SMEM (2*STAGE_U*2)

__device__ __forceinline__ size_t ymap(int m, int n, int mode) {
    if (mode == 0)
        return (((size_t)((m >> 11) * 16 + (n >> 6))) * 2048 + (m & 2047)) * 64 + (n & 63);
    return (size_t)m * 1024 + n;
}

__device__ __forceinline__ void gemm_core(
    const float* __restrict__ X, const float* __restrict__ W,
    float* __restrict__ Y, float scale, int mode, int bm, int bn,
    __nv_bfloat16* sh)
{
    const uint32_t sh0 = smem_u32(sh);
    const int t = threadIdx.x;
    const int warp = t >> 5, lane = t & 31;
    const int wm = (warp >> 1) * 32;
    const int wn = (warp & 1) * 64;
    const int lr = t >> 3, lc = (t & 7) * 4;

    float4 ra[4], rb[4];
    float acc[2][8][4];
    #pragma unroll
    for (int mt = 0; mt < 2; mt++)
        #pragma unroll
        for (int nt = 0; nt < 8; nt++)
            #pragma unroll
            for (int j = 0; j < 4; j++) acc[mt][nt][j] = 0.f;

    const int r8 = lane & 7, tl = lane >> 3;
    const uint32_t a_row = (uint32_t)(wm + (tl & 1) * 8 + r8);
    const uint32_t a_col = (uint32_t)((tl >> 1) * 16);
    const uint32_t b_row = (uint32_t)(wn + r8);
    const uint32_t b_col = (uint32_t)((tl & 1) * 16);

    #define GEMM_LDG(c) do {                                                     \
        const float* xp = X + (size_t)(bm + lr) * 1024 + (c) * 32 + lc;          \
        const float* wp = W + (size_t)(bn + lr) * 1024 + (c) * 32 + lc;          \
        _Pragma("unroll")                                                        \
        for (int p = 0; p < 4; p++) {                                            \
            ra[p] = *(const float4*)(xp + (size_t)p * 32 * 1024);                \
            rb[p] = *(const float4*)(wp + (size_t)p * 32 * 1024);                \
        }                                                                        \
    } while (0)

    #define GEMM_STS(s) do {                                                     \
        __nv_bfloat16* Ah = sh + (s) * STAGE_U;                                  \
        __nv_bfloat16* Al = Ah + MAT_U;                                          \
        __nv_bfloat16* Bh = Ah + 2 * MAT_U;                                      \
        __nv_bfloat16* Bl = Ah + 3 * MAT_U;                                      \
        _Pragma("unroll")                                                        \
        for (int p = 0; p < 4; p++) {                                            \
            int row = lr + p * 32;                                               \
            uint2 hi, lo;                                                        \
            cvt4(hi, lo, ra[p]);                                                 \
            *(uint2*)&Ah[row * PITCH + lc] = hi;                                 \
            *(uint2*)&Al[row * PITCH + lc] = lo;                                 \
            cvt4(hi, lo, rb[p]);                                                 \
            *(uint2*)&Bh[row * PITCH + lc] = hi;                                 \
            *(uint2*)&Bl[row * PITCH + lc] = lo;                                 \
        }                                                                        \
    } while (0)

    #define GEMM_COMPUTE(s) do {                                                 \
        uint32_t Ahi = sh0 + (s) * STAGE_U * 2;                                  \
        uint32_t Alo = Ahi + MAT_U * 2;                                          \
        uint32_t Bhi = Ahi + 2 * MAT_U * 2;                                      \
        uint32_t Blo = Ahi + 3 * MAT_U * 2;                                      \
        _Pragma("unroll")                                                        \
        for (int ks = 0; ks < 2; ks++) {                                         \
            uint32_t ah[2][4], al[2][4];                                         \
            _Pragma("unroll")                                                    \
            for (int mt = 0; mt < 2; mt++) {                                     \
                uint32_t off = (a_row + mt * 16) * 80 + a_col + ks * 32;         \
                ldsm_x4(ah[mt], Ahi + off);                                      \
                ldsm_x4(al[mt], Alo + off);                                      \
            }                                                                    \
            _Pragma("unroll")                                                    \
            for (int nt = 0; nt < 8; nt++) {                                     \
                uint32_t boff = (b_row + nt * 8) * 80 + b_col + ks * 32;         \
                uint32_t bh[2], bl[2];                                           \
                ldsm_x2(bh, Bhi + boff);                                         \
                ldsm_x2(bl, Blo + boff);                                         \
                _Pragma("unroll")                                                \
                for (int mt = 0; mt < 2; mt++) {                                 \
                    mma16816(acc[mt][nt], ah[mt], bh);                           \
                    mma16816(acc[mt][nt], ah[mt], bl);                           \
                    mma16816(acc[mt][nt], al[mt], bh);                           \
                }                                                                \
            }                                                                    \
        }                                                                        \
    } while (0)

    GEMM_LDG(0);
    GEMM_STS(0);
    __syncthreads();
    for (int c = 0; c < 32; c++) {
        if (c < 31) GEMM_LDG(c + 1);
        GEMM_COMPUTE(c & 1);
        __syncthreads();
        if (c < 31) { GEMM_STS((c + 1) & 1); __syncthreads(); }
    }

    const int er = lane >> 2, ec = (lane & 3) * 2;
    #pragma unroll
    for (int mt = 0; mt < 2; mt++)
        #pragma unroll
        for (int nt = 0; nt < 8; nt++) {
            int m = bm + wm + mt * 16 + er;
            int n = bn + wn + nt * 8 + ec;
            float2 v0 = make_float2(acc[mt][nt][0] * scale, acc[mt][nt][1] * scale);
            float2 v1 = make_float2(acc[mt][nt][2] * scale, acc[mt][nt][3] * scale);
            *(float2*)&Y[ymap(m,     n, mode)] = v0;
            *(float2*)&Y[ymap(m + 8, n, mode)] = v1;
        }
}

// ---- merged Q/K/V projection: grid z selects input/weight/output ----------
__global__ __launch_bounds__(256) void qkv_gemm(
    const float* __restrict__ q, const float* __restrict__ k, const float* __restrict__ v,
    const float* __restrict__ wq, const float* __restrict__ wk, const float* __restrict__ wv,
    float* __restrict__ yq, float* __restrict__ yk, float* __restrict__ yv)
{
    extern __shared__ __nv_bfloat16 sh[];
    const int z = blockIdx.z;
    const float* X = z == 0 ? q : z == 1 ? k : v;
    const float* W = z == 0 ? wq : z == 1 ? wk : wv;
    float*       Y = z == 0 ? yq : z == 1 ? yk : yv;
    gemm_core(X, W, Y, z == 0 ? 0.125f : 1.0f, 0,
              blockIdx.y * 128, blockIdx.x * 128, sh);
}

// ---- W_O projection (own launch; runs concurrently with rescale) ----------
__global__ __launch_bounds__(256) void wo_gemm(
    const float* __restrict__ Ctx, const float* __restrict__ W_O,
    float* __restrict__ out)
{
    extern __shared__ __nv_bfloat16 sh[];
    gemm_core(Ctx, W_O, out, 1.0f, 1, blockIdx.y * 128, blockIdx.x * 128, sh);
}

// ---- rescale: zero smem, full occupancy, MLP-optimized (4 rows/iter) ------
__global__ __launch_bounds__(256) void rescale_kernel(
    float* __restrict__ attn, const float* __restrict__ L)
{
    const int t = threadIdx.x;
    const int row0 = blockIdx.x * 32;
    float4* base = (float4*)(attn + (size_t)row0 * 2048);
    #pragma unroll 1
    for (int g = 0; g < 8; g++) {
        float inv0 = 1.0f / L[row0 + g*4 + 0];
        float inv1 = 1.0f / L[row0 + g*4 + 1];
        float inv2 = 1.0f / L[row0 + g*4 + 2];
        float inv3 = 1.0f / L[row0 + g*4 + 3];
        float4* p0 = base + (size_t)(g*4 + 0) * 512;
        float4* p1 = base + (size_t)(g*4 + 1) * 512;
        float4* p2 = base + (size_t)(g*4 + 2) * 512;
        float4* p3 = base + (size_t)(g*4 + 3) * 512;
        float4 a0 = p0[t], b0 = p0[t + 256];
        float4 a1 = p1[t], b1 = p1[t + 256];
        float4 a2 = p2[t], b2 = p2[t + 256];
        float4 a3 = p3[t], b3 = p3[t + 256];
        a0.x *= inv0; a0.y *= inv0; a0.z *= inv0; a0.w *= inv0;
        b0.x *= inv0; b0.y *= inv0; b0.z *= inv0; b0.w *= inv0;
        a1.x *= inv1; a1.y *= inv1; a1.z *= inv1; a1.w *= inv1;
        b1.x *= inv1; b1.y *= inv1; b1.z *= inv1; b1.w *= inv1;
        a2.x *= inv2; a2.y *= inv2; a2.z *= inv2; a2.w *= inv2;
        b2.x *= inv2; b2.y *= inv2; b2.z *= inv2; b2.w *= inv2;
        a3.x *= inv3; a3.y *= inv3; a3.z *= inv3; a3.w *= inv3;
        b3.x *= inv3; b3.y *= inv3; b3.z *= inv3; b3.w *= inv3;
        p0[t] = a0; p0[t + 256] = b0;
        p1[t] = a1; p1[t + 256] = b1;
        p2[t] = a2; p2[t + 256] = b2;
        p3[t] = a3; p3[t + 256] = b3;
    }
}

// ===========================================================================
// Tensor-core attention (R5-exact, measured 474us): 256 thr, 4q x 2k warps,
// 64-key chunks, in-loop split-bf16 conversion. Writes UNNORMALIZED attn,
// row sums to g_L, normalized context to g_C.
// ===========================================================================
#define AQHI 0
#define AQLO 18432
#define AKHI 36864
#define AKLO 46080
#define AVHI 55296
#define AVLO 64512
#define ALP  73728
#define AMSK 74752
#define AT_SMEM 75008
#define APB 144                       /* bytes per 72-bf16 row */

__global__ __launch_bounds__(256, 1) void attn_mma(
    const float* __restrict__ Qh, const float* __restrict__ Kh,
    const float* __restrict__ Vh, const int* __restrict__ mask,
    float* __restrict__ attn, float* __restrict__ Ctx, float* __restrict__ Lout)
{
    extern __shared__ char ash[];
    const uint32_t s0 = smem_u32(ash);
    float* Lpart = (float*)(ash + ALP);
    int*   Msk   = (int*)(ash + AMSK);

    const int t = threadIdx.x, warp = t >> 5, lane = t & 31;
    const int qw = warp >> 1, kw = warp & 1;
    const int q0 = blockIdx.x * 128, h = blockIdx.y, b = blockIdx.z;
    const int bh = b * H_ + h;
    const float* Qb = Qh + (size_t)bh * S_ * 64;
    const float* Kb = Kh + (size_t)bh * S_ * 64;
    const float* Vb = Vh + (size_t)bh * S_ * 64;

    Lpart[t] = 0.f;

    {
        const int lr = t >> 3, lc = (t & 7) * 8;
        #pragma unroll
        for (int p = 0; p < 4; p++) {
            int row = lr + 32 * p;
            const float* src = Qb + (size_t)(q0 + row) * 64 + lc;
            uint2 hi, lo;
            cvt4(hi, lo, *(const float4*)src);
            *(uint2*)(ash + AQHI + row * APB + lc * 2)     = hi;
            *(uint2*)(ash + AQLO + row * APB + lc * 2)     = lo;
            cvt4(hi, lo, *(const float4*)(src + 4));
            *(uint2*)(ash + AQHI + row * APB + lc * 2 + 8) = hi;
            *(uint2*)(ash + AQLO + row * APB + lc * 2 + 8) = lo;
        }
    }

    const int r8 = lane & 7, tl = lane >> 3;
    const int er = lane >> 2, ec = (lane & 3) * 2;
    const uint32_t a_roff = (uint32_t)((qw * 32 + (tl & 1) * 8 + r8) * APB + (tl >> 1) * 16);
    const uint32_t b_roff = (uint32_t)((kw * 32 + r8) * APB + (tl & 1) * 16);
    const uint32_t v_roff = (uint32_t)((kw * 32 + (tl & 1) * 8 + r8) * APB);

    float oacc[2][8][4];
    #pragma unroll
    for (int mt = 0; mt < 2; mt++)
        #pragma unroll
        for (int nt = 0; nt < 8; nt++)
            #pragma unroll
            for (int j = 0; j < 4; j++) oacc[mt][nt][j] = 0.f;

    for (int c = 0; c < 32; c++) {
        const int kb = c * 64;
        __syncthreads();

        {
            const int lr = t >> 3, lc = (t & 7) * 8;
            #pragma unroll
            for (int p = 0; p < 2; p++) {
                int row = lr + 32 * p;
                const float* sk = Kb + (size_t)(kb + row) * 64 + lc;
                const float* sv = Vb + (size_t)(kb + row) * 64 + lc;
                uint2 hi, lo;
                cvt4(hi, lo, *(const float4*)sk);
                *(uint2*)(ash + AKHI + row * APB + lc * 2)     = hi;
                *(uint2*)(ash + AKLO + row * APB + lc * 2)     = lo;
                cvt4(hi, lo, *(const float4*)(sk + 4));
                *(uint2*)(ash + AKHI + row * APB + lc * 2 + 8) = hi;
                *(uint2*)(ash + AKLO + row * APB + lc * 2 + 8) = lo;
                cvt4(hi, lo, *(const float4*)sv);
                *(uint2*)(ash + AVHI + row * APB + lc * 2)     = hi;
                *(uint2*)(ash + AVLO + row * APB + lc * 2)     = lo;
                cvt4(hi, lo, *(const float4*)(sv + 4));
                *(uint2*)(ash + AVHI + row * APB + lc * 2 + 8) = hi;
                *(uint2*)(ash + AVLO + row * APB + lc * 2 + 8) = lo;
            }
            if (t < 64) Msk[t] = mask[b * S_ + kb + t];
        }
        __syncthreads();

        float sc[2][4][4];
        #pragma unroll
        for (int mt = 0; mt < 2; mt++)
            #pragma unroll
            for (int nf = 0; nf < 4; nf++)
                #pragma unroll
                for (int j = 0; j < 4; j++) sc[mt][nf][j] = 0.f;

        #pragma unroll
        for (int ks = 0; ks < 4; ks++) {
            uint32_t qh_[2][4], ql_[2][4];
            #pragma unroll
            for (int mt = 0; mt < 2; mt++) {
                uint32_t off = a_roff + mt * 16 * APB + ks * 32;
                ldsm_x4(qh_[mt], s0 + AQHI + off);
                ldsm_x4(ql_[mt], s0 + AQLO + off);
            }
            #pragma unroll
            for (int nf = 0; nf < 4; nf++) {
                uint32_t boff = b_roff + nf * 8 * APB + ks * 32;
                uint32_t kh_[2], kl_[2];
                ldsm_x2(kh_, s0 + AKHI + boff);
                ldsm_x2(kl_, s0 + AKLO + boff);
                #pragma unroll
                for (int mt = 0; mt < 2; mt++) {
                    mma16816(sc[mt][nf], qh_[mt], kh_);
                    mma16816(sc[mt][nf], qh_[mt], kl_);
                    mma16816(sc[mt][nf], ql_[mt], kh_);
                }
            }
        }

        uint32_t phi[2][2][4], plo[2][2][4];
        #pragma unroll
        for (int mt = 0; mt < 2; mt++) {
            float rs0 = 0.f, rs1 = 0.f;
            #pragma unroll
            for (int nf = 0; nf < 4; nf++) {
                int col = kw * 32 + nf * 8 + ec;
                int m0 = Msk[col], m1 = Msk[col + 1];
                float p00 = m0 ? __expf(sc[mt][nf][0]) : 0.f;
                float p01 = m1 ? __expf(sc[mt][nf][1]) : 0.f;
                float p10 = m0 ? __expf(sc[mt][nf][2]) : 0.f;
                float p11 = m1 ? __expf(sc[mt][nf][3]) : 0.f;
                rs0 += p00 + p01; rs1 += p10 + p11;
                if (attn) {
                    int q = q0 + qw * 32 + mt * 16 + er;
                    size_t ro = ((size_t)bh * S_ + q) * S_ + kb + col;
                    *(float2*)&attn[ro]          = make_float2(p00, p01);
                    *(float2*)&attn[ro + 8 * S_] = make_float2(p10, p11);
                }
                int kf = nf >> 1, hf = (nf & 1) * 2;
                float h00 = bf_round(p00), h01 = bf_round(p01);
                float h10 = bf_round(p10), h11 = bf_round(p11);
                phi[mt][kf][hf]     = packbf(h00, h01);
                phi[mt][kf][hf + 1] = packbf(h10, h11);
                plo[mt][kf][hf]     = packbf(p00 - h00, p01 - h01);
                plo[mt][kf][hf + 1] = packbf(p10 - h10, p11 - h11);
            }
            rs0 += __shfl_xor_sync(0xffffffffu, rs0, 1);
            rs0 += __shfl_xor_sync(0xffffffffu, rs0, 2);
            rs1 += __shfl_xor_sync(0xffffffffu, rs1, 1);
            rs1 += __shfl_xor_sync(0xffffffffu, rs1, 2);
            if ((lane & 3) == 0) {
                int q = qw * 32 + mt * 16 + er;
                Lpart[kw * 128 + q]     += rs0;
                Lpart[kw * 128 + q + 8] += rs1;
            }
        }

        #pragma unroll
        for (int kf = 0; kf < 2; kf++) {
            #pragma unroll
            for (int nf2 = 0; nf2 < 8; nf2++) {
                uint32_t voff = v_roff + kf * 16 * APB + nf2 * 16;
                uint32_t vh_[2], vl_[2];
                ldsm_x2t(vh_, s0 + AVHI + voff);
                ldsm_x2t(vl_, s0 + AVLO + voff);
                #pragma unroll
                for (int mt = 0; mt < 2; mt++) {
                    mma16816(oacc[mt][nf2], phi[mt][kf], vh_);
                    mma16816(oacc[mt][nf2], phi[mt][kf], vl_);
                    mma16816(oacc[mt][nf2], plo[mt][kf], vh_);
                }
            }
        }
    }

    __syncthreads();
    float* Ored = (float*)(ash + AKHI);
    if (kw == 1) {
        #pragma unroll
        for (int mt = 0; mt < 2; mt++)
            #pragma unroll
            for (int nf2 = 0; nf2 < 8; nf2++) {
                int q = qw * 32 + mt * 16 + er, d = nf2 * 8 + ec;
                *(float2*)&Ored[q * 68 + d]       = make_float2(oacc[mt][nf2][0], oacc[mt][nf2][1]);
                *(float2*)&Ored[(q + 8) * 68 + d] = make_float2(oacc[mt][nf2][2], oacc[mt][nf2][3]);
            }
    }
    __syncthreads();
    if (kw == 0) {
        #pragma unroll
        for (int mt = 0; mt < 2; mt++) {
            int qA = qw * 32 + mt * 16 + er;
            float invA = 1.f / (Lpart[qA] + Lpart[128 + qA]);
            float invB = 1.f / (Lpart[qA + 8] + Lpart[128 + qA + 8]);
            #pragma unroll
            for (int nf2 = 0; nf2 < 8; nf2++) {
                int d = nf2 * 8 + ec;
                float2 oA = *(float2*)&Ored[qA * 68 + d];
                float2 oB = *(float2*)&Ored[(qA + 8) * 68 + d];
                oA.x = (oA.x + oacc[mt][nf2][0]) * invA;
                oA.y = (oA.y + oacc[mt][nf2][1]) * invA;
                oB.x = (oB.x + oacc[mt][nf2][2]) * invB;
                oB.y = (oB.y + oacc[mt][nf2][3]) * invB;
                size_t oo = ((size_t)b * S_ + q0 + qA) * D_ + h * 64 + d;
                *(float2*)&Ctx[oo]          = oA;
                *(float2*)&Ctx[oo + 8 * D_] = oB;
            }
        }
    }
    if (t < 128) Lout[(size_t)bh * S_ + q0 + t] = Lpart[t] + Lpart[128 + t];
}

// ===========================================================================
extern "C" void kernel_launch(void* const* d_in, const int* in_sizes, int n_in,
                              void* d_out, int out_size)
{
    const float* query = (const float*)d_in[0];
    const float* key   = (const float*)d_in[1];
    const float* value = (const float*)d_in[2];
    const int*   mask  = (const int*)d_in[3];
    const float* W_Q   = (const float*)d_in[4];
    const float* W_K   = (const float*)d_in[5];
    const float* W_V   = (const float*)d_in[6];
    const float* W_O   = (const float*)d_in[7];

    float* out = (float*)d_out;
    bool hasAttn = (out_size >= OUT_ELEMS + ATT_ELEMS);
    float* attn = hasAttn ? (out + OUT_ELEMS) : nullptr;

    float *gq, *gk, *gv, *gc, *gl;
    cudaGetSymbolAddress((void**)&gq, g_Q);
    cudaGetSymbolAddress((void**)&gk, g_K);
    cudaGetSymbolAddress((void**)&gv, g_V);
    cudaGetSymbolAddress((void**)&gc, g_C);
    cudaGetSymbolAddress((void**)&gl, g_L);

    static cudaStream_t s2 = nullptr;
    static cudaEvent_t evFork = nullptr, evJoin = nullptr;
    if (s2 == nullptr) {
        cudaStreamCreateWithFlags(&s2, cudaStreamNonBlocking);
        cudaEventCreateWithFlags(&evFork, cudaEventDisableTiming);
        cudaEventCreateWithFlags(&evJoin, cudaEventDisableTiming);
        cudaFuncSetAttribute((const void*)attn_mma,
                             cudaFuncAttributeMaxDynamicSharedMemorySize, AT_SMEM);
        cudaFuncSetAttribute((const void*)qkv_gemm,
                             cudaFuncAttributeMaxDynamicSharedMemorySize, GT_SMEM);
        cudaFuncSetAttribute((const void*)wo_gemm,
                             cudaFuncAttributeMaxDynamicSharedMemorySize, GT_SMEM);
    }

    qkv_gemm<<<dim3(8, 32, 3), 256, GT_SMEM>>>(query, key, value,
                                               W_Q, W_K, W_V, gq, gk, gv);
    attn_mma<<<dim3(16, 16, 2), 256, AT_SMEM>>>(gq, gk, gv, mask, attn, gc, gl);

    if (hasAttn) {
        // fork: rescale (DRAM-bound) on s2, W_O GEMM (tensor-bound) on main
        cudaEventRecord(evFork, 0);
        cudaStreamWaitEvent(s2, evFork, 0);
        rescale_kernel<<<2048, 256, 0, s2>>>(attn, gl);
        wo_gemm<<<dim3(8, 32), 256, GT_SMEM>>>(gc, W_O, out);
        cudaEventRecord(evJoin, s2);
        cudaStreamWaitEvent((cudaStream_t)0, evJoin, 0);
    } else {
        wo_gemm<<<dim3(8, 32), 256, GT_SMEM>>>(gc, W_O, out);
    }
}

// round 12
// speedup vs baseline: 1.2507x; 1.0519x over previous
#include <cuda_runtime.h>
#include <cuda_bf16.h>
#include <cstdint>

#define B_ 2
#define S_ 2048
#define D_ 1024
#define H_ 16
#define DK_ 64
#define OUT_ELEMS (B_*S_*D_)           /* 4194304  */
#define ATT_ELEMS (B_*H_*S_*S_)        /* 134217728 */

// ---------------- scratch (device globals; no allocation allowed) ----------
__device__ float g_Q[B_*H_*S_*DK_];    // [b][h][s][d], pre-scaled by 1/8
__device__ float g_K[B_*H_*S_*DK_];
__device__ float g_V[B_*H_*S_*DK_];
__device__ float g_C[B_*S_*D_];        // context, token-major
__device__ float g_L[B_*H_*S_];        // softmax row sums

__device__ __forceinline__ uint32_t smem_u32(const void* p) {
    uint32_t a;
    asm("{ .reg .u64 t; cvta.to.shared.u64 t, %1; cvt.u32.u64 %0, t; }" : "=r"(a) : "l"(p));
    return a;
}

// ---------------- mma.sync primitives (baseline PTX, no 'a' features) ------
__device__ __forceinline__ void ldsm_x4(uint32_t (&r)[4], uint32_t addr) {
    asm volatile("ldmatrix.sync.aligned.m8n8.x4.shared.b16 {%0,%1,%2,%3}, [%4];"
        : "=r"(r[0]), "=r"(r[1]), "=r"(r[2]), "=r"(r[3]) : "r"(addr));
}
__device__ __forceinline__ void ldsm_x2(uint32_t (&r)[2], uint32_t addr) {
    asm volatile("ldmatrix.sync.aligned.m8n8.x2.shared.b16 {%0,%1}, [%2];"
        : "=r"(r[0]), "=r"(r[1]) : "r"(addr));
}
__device__ __forceinline__ void ldsm_x2t(uint32_t (&r)[2], uint32_t addr) {
    asm volatile("ldmatrix.sync.aligned.m8n8.x2.trans.shared.b16 {%0,%1}, [%2];"
        : "=r"(r[0]), "=r"(r[1]) : "r"(addr));
}
__device__ __forceinline__ void mma16816(float (&c)[4], const uint32_t (&a)[4],
                                         const uint32_t (&b)[2]) {
    asm volatile("mma.sync.aligned.m16n8k16.row.col.f32.bf16.bf16.f32 "
        "{%0,%1,%2,%3}, {%4,%5,%6,%7}, {%8,%9}, {%0,%1,%2,%3};"
        : "+f"(c[0]), "+f"(c[1]), "+f"(c[2]), "+f"(c[3])
        : "r"(a[0]), "r"(a[1]), "r"(a[2]), "r"(a[3]), "r"(b[0]), "r"(b[1]));
}
__device__ __forceinline__ uint32_t packbf(float lo, float hi) {
    uint32_t r;
    asm("cvt.rn.bf16x2.f32 %0, %1, %2;" : "=r"(r) : "f"(hi), "f"(lo));
    return r;
}
__device__ __forceinline__ float bf_round(float x) {
    return __bfloat162float(__float2bfloat16(x));
}
__device__ __forceinline__ void cvt4(uint2 &hi, uint2 &lo, float4 vv) {
    float v0 = vv.x, v1 = vv.y, v2 = vv.z, v3 = vv.w;
    __nv_bfloat16 h0 = __float2bfloat16(v0), h1 = __float2bfloat16(v1);
    __nv_bfloat16 h2 = __float2bfloat16(v2), h3 = __float2bfloat16(v3);
    __nv_bfloat162 hh0(h0, h1), hh1(h2, h3);
    __nv_bfloat162 ll0(__float2bfloat16(v0 - __bfloat162float(h0)),
                       __float2bfloat16(v1 - __bfloat162float(h1)));
    __nv_bfloat162 ll1(__float2bfloat16(v2 - __bfloat162float(h2)),
                       __float2bfloat16(v3 - __bfloat162float(h3)));
    hi = make_uint2(*(uint32_t*)&hh0, *(uint32_t*)&hh1);
    lo = make_uint2(*(uint32_t*)&ll0, *(uint32_t*)&ll1);
}

// ===========================================================================
// Split-bf16 tensor-core GEMM core (inlined by callers).
// ===========================================================================
#define PITCH 40
#define MAT_U (128*PITCH)
#define STAGE_U (4*MAT_U)
#define GT_SMEM (2*STAGE_U*2)

__device__ __forceinline__ size_t ymap(int m, int n, int mode) {
    if (mode == 0)
        return (((size_t)((m >> 11) * 16 + (n >> 6))) * 2048 + (m & 2047)) * 64 + (n & 63);
    return (size_t)m * 1024 + n;
}

__device__ __forceinline__ void gemm_core(
    const float* __restrict__ X, const float* __restrict__ W,
    float* __restrict__ Y, float scale, int mode, int bm, int bn,
    __nv_bfloat16* sh)
{
    const uint32_t sh0 = smem_u32(sh);
    const int t = threadIdx.x;
    const int warp = t >> 5, lane = t & 31;
    const int wm = (warp >> 1) * 32;
    const int wn = (warp & 1) * 64;
    const int lr = t >> 3, lc = (t & 7) * 4;

    float4 ra[4], rb[4];
    float acc[2][8][4];
    #pragma unroll
    for (int mt = 0; mt < 2; mt++)
        #pragma unroll
        for (int nt = 0; nt < 8; nt++)
            #pragma unroll
            for (int j = 0; j < 4; j++) acc[mt][nt][j] = 0.f;

    const int r8 = lane & 7, tl = lane >> 3;
    const uint32_t a_row = (uint32_t)(wm + (tl & 1) * 8 + r8);
    const uint32_t a_col = (uint32_t)((tl >> 1) * 16);
    const uint32_t b_row = (uint32_t)(wn + r8);
    const uint32_t b_col = (uint32_t)((tl & 1) * 16);

    #define GEMM_LDG(c) do {                                                     \
        const float* xp = X + (size_t)(bm + lr) * 1024 + (c) * 32 + lc;          \
        const float* wp = W + (size_t)(bn + lr) * 1024 + (c) * 32 + lc;          \
        _Pragma("unroll")                                                        \
        for (int p = 0; p < 4; p++) {                                            \
            ra[p] = *(const float4*)(xp + (size_t)p * 32 * 1024);                \
            rb[p] = *(const float4*)(wp + (size_t)p * 32 * 1024);                \
        }                                                                        \
    } while (0)

    #define GEMM_STS(s) do {                                                     \
        __nv_bfloat16* Ah = sh + (s) * STAGE_U;                                  \
        __nv_bfloat16* Al = Ah + MAT_U;                                          \
        __nv_bfloat16* Bh = Ah + 2 * MAT_U;                                      \
        __nv_bfloat16* Bl = Ah + 3 * MAT_U;                                      \
        _Pragma("unroll")                                                        \
        for (int p = 0; p < 4; p++) {                                            \
            int row = lr + p * 32;                                               \
            uint2 hi, lo;                                                        \
            cvt4(hi, lo, ra[p]);                                                 \
            *(uint2*)&Ah[row * PITCH + lc] = hi;                                 \
            *(uint2*)&Al[row * PITCH + lc] = lo;                                 \
            cvt4(hi, lo, rb[p]);                                                 \
            *(uint2*)&Bh[row * PITCH + lc] = hi;                                 \
            *(uint2*)&Bl[row * PITCH + lc] = lo;                                 \
        }                                                                        \
    } while (0)

    #define GEMM_COMPUTE(s) do {                                                 \
        uint32_t Ahi = sh0 + (s) * STAGE_U * 2;                                  \
        uint32_t Alo = Ahi + MAT_U * 2;                                          \
        uint32_t Bhi = Ahi + 2 * MAT_U * 2;                                      \
        uint32_t Blo = Ahi + 3 * MAT_U * 2;                                      \
        _Pragma("unroll")                                                        \
        for (int ks = 0; ks < 2; ks++) {                                         \
            uint32_t ah[2][4], al[2][4];                                         \
            _Pragma("unroll")                                                    \
            for (int mt = 0; mt < 2; mt++) {                                     \
                uint32_t off = (a_row + mt * 16) * 80 + a_col + ks * 32;         \
                ldsm_x4(ah[mt], Ahi + off);                                      \
                ldsm_x4(al[mt], Alo + off);                                      \
            }                                                                    \
            _Pragma("unroll")                                                    \
            for (int nt = 0; nt < 8; nt++) {                                     \
                uint32_t boff = (b_row + nt * 8) * 80 + b_col + ks * 32;         \
                uint32_t bh[2], bl[2];                                           \
                ldsm_x2(bh, Bhi + boff);                                         \
                ldsm_x2(bl, Blo + boff);                                         \
                _Pragma("unroll")                                                \
                for (int mt = 0; mt < 2; mt++) {                                 \
                    mma16816(acc[mt][nt], ah[mt], bh);                           \
                    mma16816(acc[mt][nt], ah[mt], bl);                           \
                    mma16816(acc[mt][nt], al[mt], bh);                           \
                }                                                                \
            }                                                                    \
        }                                                                        \
    } while (0)

    GEMM_LDG(0);
    GEMM_STS(0);
    __syncthreads();
    for (int c = 0; c < 32; c++) {
        if (c < 31) GEMM_LDG(c + 1);
        GEMM_COMPUTE(c & 1);
        __syncthreads();
        if (c < 31) { GEMM_STS((c + 1) & 1); __syncthreads(); }
    }

    const int er = lane >> 2, ec = (lane & 3) * 2;
    #pragma unroll
    for (int mt = 0; mt < 2; mt++)
        #pragma unroll
        for (int nt = 0; nt < 8; nt++) {
            int m = bm + wm + mt * 16 + er;
            int n = bn + wn + nt * 8 + ec;
            float2 v0 = make_float2(acc[mt][nt][0] * scale, acc[mt][nt][1] * scale);
            float2 v1 = make_float2(acc[mt][nt][2] * scale, acc[mt][nt][3] * scale);
            *(float2*)&Y[ymap(m,     n, mode)] = v0;
            *(float2*)&Y[ymap(m + 8, n, mode)] = v1;
        }
}

// ---- merged Q/K/V projection: grid z selects input/weight/output ----------
__global__ __launch_bounds__(256) void qkv_gemm(
    const float* __restrict__ q, const float* __restrict__ k, const float* __restrict__ v,
    const float* __restrict__ wq, const float* __restrict__ wk, const float* __restrict__ wv,
    float* __restrict__ yq, float* __restrict__ yk, float* __restrict__ yv)
{
    extern __shared__ __nv_bfloat16 sh[];
    const int z = blockIdx.z;
    const float* X = z == 0 ? q : z == 1 ? k : v;
    const float* W = z == 0 ? wq : z == 1 ? wk : wv;
    float*       Y = z == 0 ? yq : z == 1 ? yk : yv;
    gemm_core(X, W, Y, z == 0 ? 0.125f : 1.0f, 0,
              blockIdx.y * 128, blockIdx.x * 128, sh);
}

// ---- W_O projection (own launch; runs concurrently with rescale) ----------
__global__ __launch_bounds__(256) void wo_gemm(
    const float* __restrict__ Ctx, const float* __restrict__ W_O,
    float* __restrict__ out)
{
    extern __shared__ __nv_bfloat16 sh[];
    gemm_core(Ctx, W_O, out, 1.0f, 1, blockIdx.y * 128, blockIdx.x * 128, sh);
}

// ---- rescale: zero smem, full occupancy, MLP-optimized (4 rows/iter) ------
__global__ __launch_bounds__(256) void rescale_kernel(
    float* __restrict__ attn, const float* __restrict__ L)
{
    const int t = threadIdx.x;
    const int row0 = blockIdx.x * 32;
    float4* base = (float4*)(attn + (size_t)row0 * 2048);
    #pragma unroll 1
    for (int g = 0; g < 8; g++) {
        float inv0 = 1.0f / L[row0 + g*4 + 0];
        float inv1 = 1.0f / L[row0 + g*4 + 1];
        float inv2 = 1.0f / L[row0 + g*4 + 2];
        float inv3 = 1.0f / L[row0 + g*4 + 3];
        float4* p0 = base + (size_t)(g*4 + 0) * 512;
        float4* p1 = base + (size_t)(g*4 + 1) * 512;
        float4* p2 = base + (size_t)(g*4 + 2) * 512;
        float4* p3 = base + (size_t)(g*4 + 3) * 512;
        float4 a0 = p0[t], b0 = p0[t + 256];
        float4 a1 = p1[t], b1 = p1[t + 256];
        float4 a2 = p2[t], b2 = p2[t + 256];
        float4 a3 = p3[t], b3 = p3[t + 256];
        a0.x *= inv0; a0.y *= inv0; a0.z *= inv0; a0.w *= inv0;
        b0.x *= inv0; b0.y *= inv0; b0.z *= inv0; b0.w *= inv0;
        a1.x *= inv1; a1.y *= inv1; a1.z *= inv1; a1.w *= inv1;
        b1.x *= inv1; b1.y *= inv1; b1.z *= inv1; b1.w *= inv1;
        a2.x *= inv2; a2.y *= inv2; a2.z *= inv2; a2.w *= inv2;
        b2.x *= inv2; b2.y *= inv2; b2.z *= inv2; b2.w *= inv2;
        a3.x *= inv3; a3.y *= inv3; a3.z *= inv3; a3.w *= inv3;
        b3.x *= inv3; b3.y *= inv3; b3.z *= inv3; b3.w *= inv3;
        p0[t] = a0; p0[t + 256] = b0;
        p1[t] = a1; p1[t + 256] = b1;
        p2[t] = a2; p2[t + 256] = b2;
        p3[t] = a3; p3[t + 256] = b3;
    }
}

// ===========================================================================
// Tensor-core attention: R10 config + Q-FRAGMENT HOISTING (Q frags loaded
// into registers once; QK loop is pure K-ldsm + MMA).
// ===========================================================================
#define AQHI 0
#define AQLO 18432
#define AKHI 36864
#define AKLO 46080
#define AVHI 55296
#define AVLO 64512
#define ALP  73728
#define AMSK 74752
#define AT_SMEM 75008
#define APB 144                       /* bytes per 72-bf16 row */

__global__ __launch_bounds__(256, 1) void attn_mma(
    const float* __restrict__ Qh, const float* __restrict__ Kh,
    const float* __restrict__ Vh, const int* __restrict__ mask,
    float* __restrict__ attn, float* __restrict__ Ctx, float* __restrict__ Lout)
{
    extern __shared__ char ash[];
    const uint32_t s0 = smem_u32(ash);
    float* Lpart = (float*)(ash + ALP);
    int*   Msk   = (int*)(ash + AMSK);

    const int t = threadIdx.x, warp = t >> 5, lane = t & 31;
    const int qw = warp >> 1, kw = warp & 1;
    const int q0 = blockIdx.x * 128, h = blockIdx.y, b = blockIdx.z;
    const int bh = b * H_ + h;
    const float* Qb = Qh + (size_t)bh * S_ * 64;
    const float* Kb = Kh + (size_t)bh * S_ * 64;
    const float* Vb = Vh + (size_t)bh * S_ * 64;

    Lpart[t] = 0.f;

    // ---- load Q tile (128x64) -> Qhi/Qlo smem ----
    {
        const int lr = t >> 3, lc = (t & 7) * 8;
        #pragma unroll
        for (int p = 0; p < 4; p++) {
            int row = lr + 32 * p;
            const float* src = Qb + (size_t)(q0 + row) * 64 + lc;
            uint2 hi, lo;
            cvt4(hi, lo, *(const float4*)src);
            *(uint2*)(ash + AQHI + row * APB + lc * 2)     = hi;
            *(uint2*)(ash + AQLO + row * APB + lc * 2)     = lo;
            cvt4(hi, lo, *(const float4*)(src + 4));
            *(uint2*)(ash + AQHI + row * APB + lc * 2 + 8) = hi;
            *(uint2*)(ash + AQLO + row * APB + lc * 2 + 8) = lo;
        }
    }

    const int r8 = lane & 7, tl = lane >> 3;
    const int er = lane >> 2, ec = (lane & 3) * 2;
    const uint32_t a_roff = (uint32_t)((qw * 32 + (tl & 1) * 8 + r8) * APB + (tl >> 1) * 16);
    const uint32_t b_roff = (uint32_t)((kw * 32 + r8) * APB + (tl & 1) * 16);
    const uint32_t v_roff = (uint32_t)((kw * 32 + (tl & 1) * 8 + r8) * APB);

    // ---- hoist Q fragments into registers (chunk-invariant) ----
    __syncthreads();
    uint32_t qh_r[2][4][4], ql_r[2][4][4];   // [mt][ks][frag]
    #pragma unroll
    for (int mt = 0; mt < 2; mt++)
        #pragma unroll
        for (int ks = 0; ks < 4; ks++) {
            uint32_t off = a_roff + mt * 16 * APB + ks * 32;
            ldsm_x4(qh_r[mt][ks], s0 + AQHI + off);
            ldsm_x4(ql_r[mt][ks], s0 + AQLO + off);
        }

    float oacc[2][8][4];
    #pragma unroll
    for (int mt = 0; mt < 2; mt++)
        #pragma unroll
        for (int nt = 0; nt < 8; nt++)
            #pragma unroll
            for (int j = 0; j < 4; j++) oacc[mt][nt][j] = 0.f;

    for (int c = 0; c < 32; c++) {
        const int kb = c * 64;
        __syncthreads();               // prev chunk compute done

        {
            const int lr = t >> 3, lc = (t & 7) * 8;
            #pragma unroll
            for (int p = 0; p < 2; p++) {
                int row = lr + 32 * p;
                const float* sk = Kb + (size_t)(kb + row) * 64 + lc;
                const float* sv = Vb + (size_t)(kb + row) * 64 + lc;
                uint2 hi, lo;
                cvt4(hi, lo, *(const float4*)sk);
                *(uint2*)(ash + AKHI + row * APB + lc * 2)     = hi;
                *(uint2*)(ash + AKLO + row * APB + lc * 2)     = lo;
                cvt4(hi, lo, *(const float4*)(sk + 4));
                *(uint2*)(ash + AKHI + row * APB + lc * 2 + 8) = hi;
                *(uint2*)(ash + AKLO + row * APB + lc * 2 + 8) = lo;
                cvt4(hi, lo, *(const float4*)sv);
                *(uint2*)(ash + AVHI + row * APB + lc * 2)     = hi;
                *(uint2*)(ash + AVLO + row * APB + lc * 2)     = lo;
                cvt4(hi, lo, *(const float4*)(sv + 4));
                *(uint2*)(ash + AVHI + row * APB + lc * 2 + 8) = hi;
                *(uint2*)(ash + AVLO + row * APB + lc * 2 + 8) = lo;
            }
            if (t < 64) Msk[t] = mask[b * S_ + kb + t];
        }
        __syncthreads();

        // ---- S = Q K^T (32q x 32k per warp), Q frags from registers ----
        float sc[2][4][4];
        #pragma unroll
        for (int mt = 0; mt < 2; mt++)
            #pragma unroll
            for (int nf = 0; nf < 4; nf++)
                #pragma unroll
                for (int j = 0; j < 4; j++) sc[mt][nf][j] = 0.f;

        #pragma unroll
        for (int ks = 0; ks < 4; ks++) {
            #pragma unroll
            for (int nf = 0; nf < 4; nf++) {
                uint32_t boff = b_roff + nf * 8 * APB + ks * 32;
                uint32_t kh_[2], kl_[2];
                ldsm_x2(kh_, s0 + AKHI + boff);
                ldsm_x2(kl_, s0 + AKLO + boff);
                #pragma unroll
                for (int mt = 0; mt < 2; mt++) {
                    mma16816(sc[mt][nf], qh_r[mt][ks], kh_);
                    mma16816(sc[mt][nf], qh_r[mt][ks], kl_);
                    mma16816(sc[mt][nf], ql_r[mt][ks], kh_);
                }
            }
        }

        // ---- epilogue: mask+exp, row sums, attn store, P frags ----
        uint32_t phi[2][2][4], plo[2][2][4];
        #pragma unroll
        for (int mt = 0; mt < 2; mt++) {
            float rs0 = 0.f, rs1 = 0.f;
            #pragma unroll
            for (int nf = 0; nf < 4; nf++) {
                int col = kw * 32 + nf * 8 + ec;
                int m0 = Msk[col], m1 = Msk[col + 1];
                float p00 = m0 ? __expf(sc[mt][nf][0]) : 0.f;
                float p01 = m1 ? __expf(sc[mt][nf][1]) : 0.f;
                float p10 = m0 ? __expf(sc[mt][nf][2]) : 0.f;
                float p11 = m1 ? __expf(sc[mt][nf][3]) : 0.f;
                rs0 += p00 + p01; rs1 += p10 + p11;
                if (attn) {
                    int q = q0 + qw * 32 + mt * 16 + er;
                    size_t ro = ((size_t)bh * S_ + q) * S_ + kb + col;
                    *(float2*)&attn[ro]          = make_float2(p00, p01);
                    *(float2*)&attn[ro + 8 * S_] = make_float2(p10, p11);
                }
                int kf = nf >> 1, hf = (nf & 1) * 2;
                float h00 = bf_round(p00), h01 = bf_round(p01);
                float h10 = bf_round(p10), h11 = bf_round(p11);
                phi[mt][kf][hf]     = packbf(h00, h01);
                phi[mt][kf][hf + 1] = packbf(h10, h11);
                plo[mt][kf][hf]     = packbf(p00 - h00, p01 - h01);
                plo[mt][kf][hf + 1] = packbf(p10 - h10, p11 - h11);
            }
            rs0 += __shfl_xor_sync(0xffffffffu, rs0, 1);
            rs0 += __shfl_xor_sync(0xffffffffu, rs0, 2);
            rs1 += __shfl_xor_sync(0xffffffffu, rs1, 1);
            rs1 += __shfl_xor_sync(0xffffffffu, rs1, 2);
            if ((lane & 3) == 0) {
                int q = qw * 32 + mt * 16 + er;
                Lpart[kw * 128 + q]     += rs0;
                Lpart[kw * 128 + q + 8] += rs1;
            }
        }

        // ---- O += P V (keys slice of this warp), split 3-term ----
        #pragma unroll
        for (int kf = 0; kf < 2; kf++) {
            #pragma unroll
            for (int nf2 = 0; nf2 < 8; nf2++) {
                uint32_t voff = v_roff + kf * 16 * APB + nf2 * 16;
                uint32_t vh_[2], vl_[2];
                ldsm_x2t(vh_, s0 + AVHI + voff);
                ldsm_x2t(vl_, s0 + AVLO + voff);
                #pragma unroll
                for (int mt = 0; mt < 2; mt++) {
                    mma16816(oacc[mt][nf2], phi[mt][kf], vh_);
                    mma16816(oacc[mt][nf2], phi[mt][kf], vl_);
                    mma16816(oacc[mt][nf2], plo[mt][kf], vh_);
                }
            }
        }
    }

    __syncthreads();
    float* Ored = (float*)(ash + AKHI);
    if (kw == 1) {
        #pragma unroll
        for (int mt = 0; mt < 2; mt++)
            #pragma unroll
            for (int nf2 = 0; nf2 < 8; nf2++) {
                int q = qw * 32 + mt * 16 + er, d = nf2 * 8 + ec;
                *(float2*)&Ored[q * 68 + d]       = make_float2(oacc[mt][nf2][0], oacc[mt][nf2][1]);
                *(float2*)&Ored[(q + 8) * 68 + d] = make_float2(oacc[mt][nf2][2], oacc[mt][nf2][3]);
            }
    }
    __syncthreads();
    if (kw == 0) {
        #pragma unroll
        for (int mt = 0; mt < 2; mt++) {
            int qA = qw * 32 + mt * 16 + er;
            float invA = 1.f / (Lpart[qA] + Lpart[128 + qA]);
            float invB = 1.f / (Lpart[qA + 8] + Lpart[128 + qA + 8]);
            #pragma unroll
            for (int nf2 = 0; nf2 < 8; nf2++) {
                int d = nf2 * 8 + ec;
                float2 oA = *(float2*)&Ored[qA * 68 + d];
                float2 oB = *(float2*)&Ored[(qA + 8) * 68 + d];
                oA.x = (oA.x + oacc[mt][nf2][0]) * invA;
                oA.y = (oA.y + oacc[mt][nf2][1]) * invA;
                oB.x = (oB.x + oacc[mt][nf2][2]) * invB;
                oB.y = (oB.y + oacc[mt][nf2][3]) * invB;
                size_t oo = ((size_t)b * S_ + q0 + qA) * D_ + h * 64 + d;
                *(float2*)&Ctx[oo]          = oA;
                *(float2*)&Ctx[oo + 8 * D_] = oB;
            }
        }
    }
    if (t < 128) Lout[(size_t)bh * S_ + q0 + t] = Lpart[t] + Lpart[128 + t];
}

// ===========================================================================
extern "C" void kernel_launch(void* const* d_in, const int* in_sizes, int n_in,
                              void* d_out, int out_size)
{
    const float* query = (const float*)d_in[0];
    const float* key   = (const float*)d_in[1];
    const float* value = (const float*)d_in[2];
    const int*   mask  = (const int*)d_in[3];
    const float* W_Q   = (const float*)d_in[4];
    const float* W_K   = (const float*)d_in[5];
    const float* W_V   = (const float*)d_in[6];
    const float* W_O   = (const float*)d_in[7];

    float* out = (float*)d_out;
    bool hasAttn = (out_size >= OUT_ELEMS + ATT_ELEMS);
    float* attn = hasAttn ? (out + OUT_ELEMS) : nullptr;

    float *gq, *gk, *gv, *gc, *gl;
    cudaGetSymbolAddress((void**)&gq, g_Q);
    cudaGetSymbolAddress((void**)&gk, g_K);
    cudaGetSymbolAddress((void**)&gv, g_V);
    cudaGetSymbolAddress((void**)&gc, g_C);
    cudaGetSymbolAddress((void**)&gl, g_L);

    static cudaStream_t s2 = nullptr;
    static cudaEvent_t evFork = nullptr, evJoin = nullptr;
    if (s2 == nullptr) {
        cudaStreamCreateWithFlags(&s2, cudaStreamNonBlocking);
        cudaEventCreateWithFlags(&evFork, cudaEventDisableTiming);
        cudaEventCreateWithFlags(&evJoin, cudaEventDisableTiming);
        cudaFuncSetAttribute((const void*)attn_mma,
                             cudaFuncAttributeMaxDynamicSharedMemorySize, AT_SMEM);
        cudaFuncSetAttribute((const void*)qkv_gemm,
                             cudaFuncAttributeMaxDynamicSharedMemorySize, GT_SMEM);
        cudaFuncSetAttribute((const void*)wo_gemm,
                             cudaFuncAttributeMaxDynamicSharedMemorySize, GT_SMEM);
    }

    qkv_gemm<<<dim3(8, 32, 3), 256, GT_SMEM>>>(query, key, value,
                                               W_Q, W_K, W_V, gq, gk, gv);
    attn_mma<<<dim3(16, 16, 2), 256, AT_SMEM>>>(gq, gk, gv, mask, attn, gc, gl);

    if (hasAttn) {
        // fork: rescale (DRAM-bound) on s2, W_O GEMM (tensor-bound) on main
        cudaEventRecord(evFork, 0);
        cudaStreamWaitEvent(s2, evFork, 0);
        rescale_kernel<<<2048, 256, 0, s2>>>(attn, gl);
        wo_gemm<<<dim3(8, 32), 256, GT_SMEM>>>(gc, W_O, out);
        cudaEventRecord(evJoin, s2);
        cudaStreamWaitEvent((cudaStream_t)0, evJoin, 0);
    } else {
        wo_gemm<<<dim3(8, 32), 256, GT_SMEM>>>(gc, W_O, out);
    }
}

// round 13
// speedup vs baseline: 1.3136x; 1.0502x over previous
#include <cuda_runtime.h>
#include <cuda_bf16.h>
#include <cstdint>

#define B_ 2
#define S_ 2048
#define D_ 1024
#define H_ 16
#define DK_ 64
#define OUT_ELEMS (B_*S_*D_)           /* 4194304  */
#define ATT_ELEMS (B_*H_*S_*S_)        /* 134217728 */

// ---------------- scratch (device globals; no allocation allowed) ----------
__device__ float g_Q[B_*H_*S_*DK_];    // [b][h][s][d], pre-scaled by 1/8
__device__ float g_K[B_*H_*S_*DK_];
__device__ float g_V[B_*H_*S_*DK_];
__device__ float g_C[B_*S_*D_];        // context, token-major
__device__ float g_L[B_*H_*S_];        // softmax row sums

__device__ __forceinline__ uint32_t smem_u32(const void* p) {
    uint32_t a;
    asm("{ .reg .u64 t; cvta.to.shared.u64 t, %1; cvt.u32.u64 %0, t; }" : "=r"(a) : "l"(p));
    return a;
}

// ---------------- mma.sync primitives (baseline PTX, no 'a' features) ------
__device__ __forceinline__ void ldsm_x4(uint32_t (&r)[4], uint32_t addr) {
    asm volatile("ldmatrix.sync.aligned.m8n8.x4.shared.b16 {%0,%1,%2,%3}, [%4];"
        : "=r"(r[0]), "=r"(r[1]), "=r"(r[2]), "=r"(r[3]) : "r"(addr));
}
__device__ __forceinline__ void ldsm_x2(uint32_t (&r)[2], uint32_t addr) {
    asm volatile("ldmatrix.sync.aligned.m8n8.x2.shared.b16 {%0,%1}, [%2];"
        : "=r"(r[0]), "=r"(r[1]) : "r"(addr));
}
__device__ __forceinline__ void ldsm_x2t(uint32_t (&r)[2], uint32_t addr) {
    asm volatile("ldmatrix.sync.aligned.m8n8.x2.trans.shared.b16 {%0,%1}, [%2];"
        : "=r"(r[0]), "=r"(r[1]) : "r"(addr));
}
__device__ __forceinline__ void mma16816(float (&c)[4], const uint32_t (&a)[4],
                                         const uint32_t (&b)[2]) {
    asm volatile("mma.sync.aligned.m16n8k16.row.col.f32.bf16.bf16.f32 "
        "{%0,%1,%2,%3}, {%4,%5,%6,%7}, {%8,%9}, {%0,%1,%2,%3};"
        : "+f"(c[0]), "+f"(c[1]), "+f"(c[2]), "+f"(c[3])
        : "r"(a[0]), "r"(a[1]), "r"(a[2]), "r"(a[3]), "r"(b[0]), "r"(b[1]));
}
__device__ __forceinline__ uint32_t packbf(float lo, float hi) {
    uint32_t r;
    asm("cvt.rn.bf16x2.f32 %0, %1, %2;" : "=r"(r) : "f"(hi), "f"(lo));
    return r;
}
__device__ __forceinline__ float bf_round(float x) {
    return __bfloat162float(__float2bfloat16(x));
}
__device__ __forceinline__ void cvt4(uint2 &hi, uint2 &lo, float4 vv) {
    float v0 = vv.x, v1 = vv.y, v2 = vv.z, v3 = vv.w;
    __nv_bfloat16 h0 = __float2bfloat16(v0), h1 = __float2bfloat16(v1);
    __nv_bfloat16 h2 = __float2bfloat16(v2), h3 = __float2bfloat16(v3);
    __nv_bfloat162 hh0(h0, h1), hh1(h2, h3);
    __nv_bfloat162 ll0(__float2bfloat16(v0 - __bfloat162float(h0)),
                       __float2bfloat16(v1 - __bfloat162float(h1)));
    __nv_bfloat162 ll1(__float2bfloat16(v2 - __bfloat162float(h2)),
                       __float2bfloat16(v3 - __bfloat162float(h3)));
    hi = make_uint2(*(uint32_t*)&hh0, *(uint32_t*)&hh1);
    lo = make_uint2(*(uint32_t*)&ll0, *(uint32_t*)&ll1);
}

// ===========================================================================
// Split-bf16 tensor-core GEMM core (inlined by callers).
// ===========================================================================
#define PITCH 40
#define MAT_U (128*PITCH)
#define STAGE_U (4*MAT_U)
#define GT_SMEM (2*STAGE_U*2)

__device__ __forceinline__ size_t ymap(int m, int n, int mode) {
    if (mode == 0)
        return (((size_t)((m >> 11) * 16 + (n >> 6))) * 2048 + (m & 2047)) * 64 + (n & 63);
    return (size_t)m * 1024 + n;
}

__device__ __forceinline__ void gemm_core(
    const float* __restrict__ X, const float* __restrict__ W,
    float* __restrict__ Y, float scale, int mode, int bm, int bn,
    __nv_bfloat16* sh)
{
    const uint32_t sh0 = smem_u32(sh);
    const int t = threadIdx.x;
    const int warp = t >> 5, lane = t & 31;
    const int wm = (warp >> 1) * 32;
    const int wn = (warp & 1) * 64;
    const int lr = t >> 3, lc = (t & 7) * 4;

    float4 ra[4], rb[4];
    float acc[2][8][4];
    #pragma unroll
    for (int mt = 0; mt < 2; mt++)
        #pragma unroll
        for (int nt = 0; nt < 8; nt++)
            #pragma unroll
            for (int j = 0; j < 4; j++) acc[mt][nt][j] = 0.f;

    const int r8 = lane & 7, tl = lane >> 3;
    const uint32_t a_row = (uint32_t)(wm + (tl & 1) * 8 + r8);
    const uint32_t a_col = (uint32_t)((tl >> 1) * 16);
    const uint32_t b_row = (uint32_t)(wn + r8);
    const uint32_t b_col = (uint32_t)((tl & 1) * 16);

    #define GEMM_LDG(c) do {                                                     \
        const float* xp = X + (size_t)(bm + lr) * 1024 + (c) * 32 + lc;          \
        const float* wp = W + (size_t)(bn + lr) * 1024 + (c) * 32 + lc;          \
        _Pragma("unroll")                                                        \
        for (int p = 0; p < 4; p++) {                                            \
            ra[p] = *(const float4*)(xp + (size_t)p * 32 * 1024);                \
            rb[p] = *(const float4*)(wp + (size_t)p * 32 * 1024);                \
        }                                                                        \
    } while (0)

    #define GEMM_STS(s) do {                                                     \
        __nv_bfloat16* Ah = sh + (s) * STAGE_U;                                  \
        __nv_bfloat16* Al = Ah + MAT_U;                                          \
        __nv_bfloat16* Bh = Ah + 2 * MAT_U;                                      \
        __nv_bfloat16* Bl = Ah + 3 * MAT_U;                                      \
        _Pragma("unroll")                                                        \
        for (int p = 0; p < 4; p++) {                                            \
            int row = lr + p * 32;                                               \
            uint2 hi, lo;                                                        \
            cvt4(hi, lo, ra[p]);                                                 \
            *(uint2*)&Ah[row * PITCH + lc] = hi;                                 \
            *(uint2*)&Al[row * PITCH + lc] = lo;                                 \
            cvt4(hi, lo, rb[p]);                                                 \
            *(uint2*)&Bh[row * PITCH + lc] = hi;                                 \
            *(uint2*)&Bl[row * PITCH + lc] = lo;                                 \
        }                                                                        \
    } while (0)

    #define GEMM_COMPUTE(s) do {                                                 \
        uint32_t Ahi = sh0 + (s) * STAGE_U * 2;                                  \
        uint32_t Alo = Ahi + MAT_U * 2;                                          \
        uint32_t Bhi = Ahi + 2 * MAT_U * 2;                                      \
        uint32_t Blo = Ahi + 3 * MAT_U * 2;                                      \
        _Pragma("unroll")                                                        \
        for (int ks = 0; ks < 2; ks++) {                                         \
            uint32_t ah[2][4], al[2][4];                                         \
            _Pragma("unroll")                                                    \
            for (int mt = 0; mt < 2; mt++) {                                     \
                uint32_t off = (a_row + mt * 16) * 80 + a_col + ks * 32;         \
                ldsm_x4(ah[mt], Ahi + off);                                      \
                ldsm_x4(al[mt], Alo + off);                                      \
            }                                                                    \
            _Pragma("unroll")                                                    \
            for (int nt = 0; nt < 8; nt++) {                                     \
                uint32_t boff = (b_row + nt * 8) * 80 + b_col + ks * 32;         \
                uint32_t bh[2], bl[2];                                           \
                ldsm_x2(bh, Bhi + boff);                                         \
                ldsm_x2(bl, Blo + boff);                                         \
                _Pragma("unroll")                                                \
                for (int mt = 0; mt < 2; mt++) {                                 \
                    mma16816(acc[mt][nt], ah[mt], bh);                           \
                    mma16816(acc[mt][nt], ah[mt], bl);                           \
                    mma16816(acc[mt][nt], al[mt], bh);                           \
                }                                                                \
            }                                                                    \
        }                                                                        \
    } while (0)

    GEMM_LDG(0);
    GEMM_STS(0);
    __syncthreads();
    for (int c = 0; c < 32; c++) {
        if (c < 31) GEMM_LDG(c + 1);
        GEMM_COMPUTE(c & 1);
        __syncthreads();
        if (c < 31) { GEMM_STS((c + 1) & 1); __syncthreads(); }
    }

    const int er = lane >> 2, ec = (lane & 3) * 2;
    #pragma unroll
    for (int mt = 0; mt < 2; mt++)
        #pragma unroll
        for (int nt = 0; nt < 8; nt++) {
            int m = bm + wm + mt * 16 + er;
            int n = bn + wn + nt * 8 + ec;
            float2 v0 = make_float2(acc[mt][nt][0] * scale, acc[mt][nt][1] * scale);
            float2 v1 = make_float2(acc[mt][nt][2] * scale, acc[mt][nt][3] * scale);
            *(float2*)&Y[ymap(m,     n, mode)] = v0;
            *(float2*)&Y[ymap(m + 8, n, mode)] = v1;
        }
}

// ---- merged Q/K/V projection: grid z selects input/weight/output ----------
__global__ __launch_bounds__(256) void qkv_gemm(
    const float* __restrict__ q, const float* __restrict__ k, const float* __restrict__ v,
    const float* __restrict__ wq, const float* __restrict__ wk, const float* __restrict__ wv,
    float* __restrict__ yq, float* __restrict__ yk, float* __restrict__ yv)
{
    extern __shared__ __nv_bfloat16 sh[];
    const int z = blockIdx.z;
    const float* X = z == 0 ? q : z == 1 ? k : v;
    const float* W = z == 0 ? wq : z == 1 ? wk : wv;
    float*       Y = z == 0 ? yq : z == 1 ? yk : yv;
    gemm_core(X, W, Y, z == 0 ? 0.125f : 1.0f, 0,
              blockIdx.y * 128, blockIdx.x * 128, sh);
}

// ---- W_O projection (own launch; runs concurrently with rescale) ----------
__global__ __launch_bounds__(256) void wo_gemm(
    const float* __restrict__ Ctx, const float* __restrict__ W_O,
    float* __restrict__ out)
{
    extern __shared__ __nv_bfloat16 sh[];
    gemm_core(Ctx, W_O, out, 1.0f, 1, blockIdx.y * 128, blockIdx.x * 128, sh);
}

// ---- rescale: zero smem, full occupancy, MLP-optimized (4 rows/iter) ------
__global__ __launch_bounds__(256) void rescale_kernel(
    float* __restrict__ attn, const float* __restrict__ L)
{
    const int t = threadIdx.x;
    const int row0 = blockIdx.x * 32;
    float4* base = (float4*)(attn + (size_t)row0 * 2048);
    #pragma unroll 1
    for (int g = 0; g < 8; g++) {
        float inv0 = 1.0f / L[row0 + g*4 + 0];
        float inv1 = 1.0f / L[row0 + g*4 + 1];
        float inv2 = 1.0f / L[row0 + g*4 + 2];
        float inv3 = 1.0f / L[row0 + g*4 + 3];
        float4* p0 = base + (size_t)(g*4 + 0) * 512;
        float4* p1 = base + (size_t)(g*4 + 1) * 512;
        float4* p2 = base + (size_t)(g*4 + 2) * 512;
        float4* p3 = base + (size_t)(g*4 + 3) * 512;
        float4 a0 = p0[t], b0 = p0[t + 256];
        float4 a1 = p1[t], b1 = p1[t + 256];
        float4 a2 = p2[t], b2 = p2[t + 256];
        float4 a3 = p3[t], b3 = p3[t + 256];
        a0.x *= inv0; a0.y *= inv0; a0.z *= inv0; a0.w *= inv0;
        b0.x *= inv0; b0.y *= inv0; b0.z *= inv0; b0.w *= inv0;
        a1.x *= inv1; a1.y *= inv1; a1.z *= inv1; a1.w *= inv1;
        b1.x *= inv1; b1.y *= inv1; b1.z *= inv1; b1.w *= inv1;
        a2.x *= inv2; a2.y *= inv2; a2.z *= inv2; a2.w *= inv2;
        b2.x *= inv2; b2.y *= inv2; b2.z *= inv2; b2.w *= inv2;
        a3.x *= inv3; a3.y *= inv3; a3.z *= inv3; a3.w *= inv3;
        b3.x *= inv3; b3.y *= inv3; b3.z *= inv3; b3.w *= inv3;
        p0[t] = a0; p0[t + 256] = b0;
        p1[t] = a1; p1[t + 256] = b1;
        p2[t] = a2; p2[t + 256] = b2;
        p3[t] = a3; p3[t + 256] = b3;
    }
}

// ===========================================================================
// Tensor-core attention: Q-fragment hoisting + DOUBLE-BUFFERED K/V stages
// with register prefetch (LDG chunk c+1 issued before compute of chunk c,
// STS to the other stage after compute, ONE barrier per iteration).
// ===========================================================================
#define APB 144                        /* bytes per 72-bf16 row */
#define AQHI 0
#define AQLO 18432
#define ASKV 36864                     /* K/V stages base */
#define ASTG 36864                     /* per-stage: Khi,Klo,Vhi,Vlo x 9216 */
#define ALP  (ASKV + 2*ASTG)           /* 110592: 256 f32 partials */
#define AMSK (ALP + 1024)              /* 111616: 2 x 64 ints */
#define AT_SMEM (AMSK + 512)           /* 112128 */

__global__ __launch_bounds__(256, 1) void attn_mma(
    const float* __restrict__ Qh, const float* __restrict__ Kh,
    const float* __restrict__ Vh, const int* __restrict__ mask,
    float* __restrict__ attn, float* __restrict__ Ctx, float* __restrict__ Lout)
{
    extern __shared__ char ash[];
    const uint32_t s0 = smem_u32(ash);
    float* Lpart = (float*)(ash + ALP);
    int*   Msk   = (int*)(ash + AMSK);

    const int t = threadIdx.x, warp = t >> 5, lane = t & 31;
    const int qw = warp >> 1, kw = warp & 1;
    const int q0 = blockIdx.x * 128, h = blockIdx.y, b = blockIdx.z;
    const int bh = b * H_ + h;
    const float* Qb = Qh + (size_t)bh * S_ * 64;
    const float* Kb = Kh + (size_t)bh * S_ * 64;
    const float* Vb = Vh + (size_t)bh * S_ * 64;

    Lpart[t] = 0.f;

    const int lr = t >> 3, lc = (t & 7) * 8;

    // ---- load Q tile (128x64) -> Qhi/Qlo smem ----
    #pragma unroll
    for (int p = 0; p < 4; p++) {
        int row = lr + 32 * p;
        const float* src = Qb + (size_t)(q0 + row) * 64 + lc;
        uint2 hi, lo;
        cvt4(hi, lo, *(const float4*)src);
        *(uint2*)(ash + AQHI + row * APB + lc * 2)     = hi;
        *(uint2*)(ash + AQLO + row * APB + lc * 2)     = lo;
        cvt4(hi, lo, *(const float4*)(src + 4));
        *(uint2*)(ash + AQHI + row * APB + lc * 2 + 8) = hi;
        *(uint2*)(ash + AQLO + row * APB + lc * 2 + 8) = lo;
    }

    const int r8 = lane & 7, tl = lane >> 3;
    const int er = lane >> 2, ec = (lane & 3) * 2;
    const uint32_t a_roff = (uint32_t)((qw * 32 + (tl & 1) * 8 + r8) * APB + (tl >> 1) * 16);
    const uint32_t b_roff = (uint32_t)((kw * 32 + r8) * APB + (tl & 1) * 16);
    const uint32_t v_roff = (uint32_t)((kw * 32 + (tl & 1) * 8 + r8) * APB);

    // ---- prefetch registers + macros ----
    float4 fk[4], fv[4];
    int pm = 0;

    #define AT_LDG(c) do {                                                       \
        int kb_ = (c) * 64;                                                      \
        const float* sk0 = Kb + (size_t)(kb_ + lr) * 64 + lc;                    \
        const float* sv0 = Vb + (size_t)(kb_ + lr) * 64 + lc;                    \
        fk[0] = *(const float4*)sk0;           fk[1] = *(const float4*)(sk0 + 4);\
        fk[2] = *(const float4*)(sk0 + 32*64); fk[3] = *(const float4*)(sk0 + 32*64 + 4); \
        fv[0] = *(const float4*)sv0;           fv[1] = *(const float4*)(sv0 + 4);\
        fv[2] = *(const float4*)(sv0 + 32*64); fv[3] = *(const float4*)(sv0 + 32*64 + 4); \
        if (t < 64) pm = mask[b * S_ + kb_ + t];                                 \
    } while (0)

    #define AT_STS(st) do {                                                      \
        char* kh_b = ash + ASKV + (st) * ASTG;                                   \
        _Pragma("unroll")                                                        \
        for (int p = 0; p < 2; p++) {                                            \
            int row = lr + 32 * p;                                               \
            uint2 hi, lo;                                                        \
            cvt4(hi, lo, fk[2*p]);                                               \
            *(uint2*)(kh_b + row * APB + lc * 2)              = hi;              \
            *(uint2*)(kh_b + 9216 + row * APB + lc * 2)       = lo;              \
            cvt4(hi, lo, fk[2*p + 1]);                                           \
            *(uint2*)(kh_b + row * APB + lc * 2 + 8)          = hi;              \
            *(uint2*)(kh_b + 9216 + row * APB + lc * 2 + 8)   = lo;              \
            cvt4(hi, lo, fv[2*p]);                                               \
            *(uint2*)(kh_b + 18432 + row * APB + lc * 2)      = hi;              \
            *(uint2*)(kh_b + 27648 + row * APB + lc * 2)      = lo;              \
            cvt4(hi, lo, fv[2*p + 1]);                                           \
            *(uint2*)(kh_b + 18432 + row * APB + lc * 2 + 8)  = hi;              \
            *(uint2*)(kh_b + 27648 + row * APB + lc * 2 + 8)  = lo;              \
        }                                                                        \
        if (t < 64) Msk[(st) * 64 + t] = pm;                                     \
    } while (0)

    // prologue: stage 0 filled, Q visible
    AT_LDG(0);
    __syncthreads();                   // Q smem writes visible for hoist

    // ---- hoist Q fragments into registers (chunk-invariant) ----
    uint32_t qh_r[2][4][4], ql_r[2][4][4];   // [mt][ks][frag]
    #pragma unroll
    for (int mt = 0; mt < 2; mt++)
        #pragma unroll
        for (int ks = 0; ks < 4; ks++) {
            uint32_t off = a_roff + mt * 16 * APB + ks * 32;
            ldsm_x4(qh_r[mt][ks], s0 + AQHI + off);
            ldsm_x4(ql_r[mt][ks], s0 + AQLO + off);
        }

    AT_STS(0);
    __syncthreads();

    float oacc[2][8][4];
    #pragma unroll
    for (int mt = 0; mt < 2; mt++)
        #pragma unroll
        for (int nt = 0; nt < 8; nt++)
            #pragma unroll
            for (int j = 0; j < 4; j++) oacc[mt][nt][j] = 0.f;

    for (int c = 0; c < 32; c++) {
        const int kb = c * 64;
        const int st = c & 1;
        const uint32_t sKh = s0 + ASKV + st * ASTG;
        const uint32_t sKl = sKh + 9216;
        const uint32_t sVh = sKh + 18432;
        const uint32_t sVl = sKh + 27648;

        if (c < 31) AT_LDG(c + 1);     // issue next chunk's loads now

        // ---- S = Q K^T (32q x 32k per warp), Q frags from registers ----
        float sc[2][4][4];
        #pragma unroll
        for (int mt = 0; mt < 2; mt++)
            #pragma unroll
            for (int nf = 0; nf < 4; nf++)
                #pragma unroll
                for (int j = 0; j < 4; j++) sc[mt][nf][j] = 0.f;

        #pragma unroll
        for (int ks = 0; ks < 4; ks++) {
            #pragma unroll
            for (int nf = 0; nf < 4; nf++) {
                uint32_t boff = b_roff + nf * 8 * APB + ks * 32;
                uint32_t kh_[2], kl_[2];
                ldsm_x2(kh_, sKh + boff);
                ldsm_x2(kl_, sKl + boff);
                #pragma unroll
                for (int mt = 0; mt < 2; mt++) {
                    mma16816(sc[mt][nf], qh_r[mt][ks], kh_);
                    mma16816(sc[mt][nf], qh_r[mt][ks], kl_);
                    mma16816(sc[mt][nf], ql_r[mt][ks], kh_);
                }
            }
        }

        // ---- epilogue: mask+exp, row sums, attn store, P frags ----
        uint32_t phi[2][2][4], plo[2][2][4];
        #pragma unroll
        for (int mt = 0; mt < 2; mt++) {
            float rs0 = 0.f, rs1 = 0.f;
            #pragma unroll
            for (int nf = 0; nf < 4; nf++) {
                int col = kw * 32 + nf * 8 + ec;
                int m0 = Msk[st * 64 + col], m1 = Msk[st * 64 + col + 1];
                float p00 = m0 ? __expf(sc[mt][nf][0]) : 0.f;
                float p01 = m1 ? __expf(sc[mt][nf][1]) : 0.f;
                float p10 = m0 ? __expf(sc[mt][nf][2]) : 0.f;
                float p11 = m1 ? __expf(sc[mt][nf][3]) : 0.f;
                rs0 += p00 + p01; rs1 += p10 + p11;
                if (attn) {
                    int q = q0 + qw * 32 + mt * 16 + er;
                    size_t ro = ((size_t)bh * S_ + q) * S_ + kb + col;
                    *(float2*)&attn[ro]          = make_float2(p00, p01);
                    *(float2*)&attn[ro + 8 * S_] = make_float2(p10, p11);
                }
                int kf = nf >> 1, hf = (nf & 1) * 2;
                float h00 = bf_round(p00), h01 = bf_round(p01);
                float h10 = bf_round(p10), h11 = bf_round(p11);
                phi[mt][kf][hf]     = packbf(h00, h01);
                phi[mt][kf][hf + 1] = packbf(h10, h11);
                plo[mt][kf][hf]     = packbf(p00 - h00, p01 - h01);
                plo[mt][kf][hf + 1] = packbf(p10 - h10, p11 - h11);
            }
            rs0 += __shfl_xor_sync(0xffffffffu, rs0, 1);
            rs0 += __shfl_xor_sync(0xffffffffu, rs0, 2);
            rs1 += __shfl_xor_sync(0xffffffffu, rs1, 1);
            rs1 += __shfl_xor_sync(0xffffffffu, rs1, 2);
            if ((lane & 3) == 0) {
                int q = qw * 32 + mt * 16 + er;
                Lpart[kw * 128 + q]     += rs0;
                Lpart[kw * 128 + q + 8] += rs1;
            }
        }

        // ---- O += P V (keys slice of this warp), split 3-term ----
        #pragma unroll
        for (int kf = 0; kf < 2; kf++) {
            #pragma unroll
            for (int nf2 = 0; nf2 < 8; nf2++) {
                uint32_t voff = v_roff + kf * 16 * APB + nf2 * 16;
                uint32_t vh_[2], vl_[2];
                ldsm_x2t(vh_, sVh + voff);
                ldsm_x2t(vl_, sVl + voff);
                #pragma unroll
                for (int mt = 0; mt < 2; mt++) {
                    mma16816(oacc[mt][nf2], phi[mt][kf], vh_);
                    mma16816(oacc[mt][nf2], phi[mt][kf], vl_);
                    mma16816(oacc[mt][nf2], plo[mt][kf], vh_);
                }
            }
        }

        // ---- store prefetched chunk into the OTHER stage, one barrier ----
        if (c < 31) AT_STS((c + 1) & 1);
        __syncthreads();
    }

    // ---- reduce O across the 2 k-warps via smem, normalize, write ----
    float* Ored = (float*)(ash + ASKV);        // reuse stage area
    if (kw == 1) {
        #pragma unroll
        for (int mt = 0; mt < 2; mt++)
            #pragma unroll
            for (int nf2 = 0; nf2 < 8; nf2++) {
                int q = qw * 32 + mt * 16 + er, d = nf2 * 8 + ec;
                *(float2*)&Ored[q * 68 + d]       = make_float2(oacc[mt][nf2][0], oacc[mt][nf2][1]);
                *(float2*)&Ored[(q + 8) * 68 + d] = make_float2(oacc[mt][nf2][2], oacc[mt][nf2][3]);
            }
    }
    __syncthreads();
    if (kw == 0) {
        #pragma unroll
        for (int mt = 0; mt < 2; mt++) {
            int qA = qw * 32 + mt * 16 + er;
            float invA = 1.f / (Lpart[qA] + Lpart[128 + qA]);
            float invB = 1.f / (Lpart[qA + 8] + Lpart[128 + qA + 8]);
            #pragma unroll
            for (int nf2 = 0; nf2 < 8; nf2++) {
                int d = nf2 * 8 + ec;
                float2 oA = *(float2*)&Ored[qA * 68 + d];
                float2 oB = *(float2*)&Ored[(qA + 8) * 68 + d];
                oA.x = (oA.x + oacc[mt][nf2][0]) * invA;
                oA.y = (oA.y + oacc[mt][nf2][1]) * invA;
                oB.x = (oB.x + oacc[mt][nf2][2]) * invB;
                oB.y = (oB.y + oacc[mt][nf2][3]) * invB;
                size_t oo = ((size_t)b * S_ + q0 + qA) * D_ + h * 64 + d;
                *(float2*)&Ctx[oo]          = oA;
                *(float2*)&Ctx[oo + 8 * D_] = oB;
            }
        }
    }
    if (t < 128) Lout[(size_t)bh * S_ + q0 + t] = Lpart[t] + Lpart[128 + t];
}

// ===========================================================================
extern "C" void kernel_launch(void* const* d_in, const int* in_sizes, int n_in,
                              void* d_out, int out_size)
{
    const float* query = (const float*)d_in[0];
    const float* key   = (const float*)d_in[1];
    const float* value = (const float*)d_in[2];
    const int*   mask  = (const int*)d_in[3];
    const float* W_Q   = (const float*)d_in[4];
    const float* W_K   = (const float*)d_in[5];
    const float* W_V   = (const float*)d_in[6];
    const float* W_O   = (const float*)d_in[7];

    float* out = (float*)d_out;
    bool hasAttn = (out_size >= OUT_ELEMS + ATT_ELEMS);
    float* attn = hasAttn ? (out + OUT_ELEMS) : nullptr;

    float *gq, *gk, *gv, *gc, *gl;
    cudaGetSymbolAddress((void**)&gq, g_Q);
    cudaGetSymbolAddress((void**)&gk, g_K);
    cudaGetSymbolAddress((void**)&gv, g_V);
    cudaGetSymbolAddress((void**)&gc, g_C);
    cudaGetSymbolAddress((void**)&gl, g_L);

    static cudaStream_t s2 = nullptr;
    static cudaEvent_t evFork = nullptr, evJoin = nullptr;
    if (s2 == nullptr) {
        cudaStreamCreateWithFlags(&s2, cudaStreamNonBlocking);
        cudaEventCreateWithFlags(&evFork, cudaEventDisableTiming);
        cudaEventCreateWithFlags(&evJoin, cudaEventDisableTiming);
        cudaFuncSetAttribute((const void*)attn_mma,
                             cudaFuncAttributeMaxDynamicSharedMemorySize, AT_SMEM);
        cudaFuncSetAttribute((const void*)qkv_gemm,
                             cudaFuncAttributeMaxDynamicSharedMemorySize, GT_SMEM);
        cudaFuncSetAttribute((const void*)wo_gemm,
                             cudaFuncAttributeMaxDynamicSharedMemorySize, GT_SMEM);
    }

    qkv_gemm<<<dim3(8, 32, 3), 256, GT_SMEM>>>(query, key, value,
                                               W_Q, W_K, W_V, gq, gk, gv);
    attn_mma<<<dim3(16, 16, 2), 256, AT_SMEM>>>(gq, gk, gv, mask, attn, gc, gl);

    if (hasAttn) {
        // fork: rescale (DRAM-bound) on s2, W_O GEMM (tensor-bound) on main
        cudaEventRecord(evFork, 0);
        cudaStreamWaitEvent(s2, evFork, 0);
        rescale_kernel<<<2048, 256, 0, s2>>>(attn, gl);
        wo_gemm<<<dim3(8, 32), 256, GT_SMEM>>>(gc, W_O, out);
        cudaEventRecord(evJoin, s2);
        cudaStreamWaitEvent((cudaStream_t)0, evJoin, 0);
    } else {
        wo_gemm<<<dim3(8, 32), 256, GT_SMEM>>>(gc, W_O, out);
    }
}

// round 14
// speedup vs baseline: 1.3316x; 1.0137x over previous
#include <cuda_runtime.h>
#include <cuda_bf16.h>
#include <cstdint>

#define B_ 2
#define S_ 2048
#define D_ 1024
#define H_ 16
#define DK_ 64
#define OUT_ELEMS (B_*S_*D_)           /* 4194304  */
#define ATT_ELEMS (B_*H_*S_*S_)        /* 134217728 */

// ---------------- scratch (device globals; no allocation allowed) ----------
__device__ float g_Q[B_*H_*S_*DK_];    // [b][h][s][d], pre-scaled by 1/8
__device__ float g_K[B_*H_*S_*DK_];
__device__ float g_V[B_*H_*S_*DK_];
__device__ float g_C[B_*S_*D_];        // context, token-major
__device__ float g_L[B_*H_*S_];        // softmax row sums

__device__ __forceinline__ uint32_t smem_u32(const void* p) {
    uint32_t a;
    asm("{ .reg .u64 t; cvta.to.shared.u64 t, %1; cvt.u32.u64 %0, t; }" : "=r"(a) : "l"(p));
    return a;
}

// ---------------- mma.sync primitives (baseline PTX, no 'a' features) ------
__device__ __forceinline__ void ldsm_x4(uint32_t (&r)[4], uint32_t addr) {
    asm volatile("ldmatrix.sync.aligned.m8n8.x4.shared.b16 {%0,%1,%2,%3}, [%4];"
        : "=r"(r[0]), "=r"(r[1]), "=r"(r[2]), "=r"(r[3]) : "r"(addr));
}
__device__ __forceinline__ void ldsm_x2(uint32_t (&r)[2], uint32_t addr) {
    asm volatile("ldmatrix.sync.aligned.m8n8.x2.shared.b16 {%0,%1}, [%2];"
        : "=r"(r[0]), "=r"(r[1]) : "r"(addr));
}
__device__ __forceinline__ void ldsm_x2t(uint32_t (&r)[2], uint32_t addr) {
    asm volatile("ldmatrix.sync.aligned.m8n8.x2.trans.shared.b16 {%0,%1}, [%2];"
        : "=r"(r[0]), "=r"(r[1]) : "r"(addr));
}
__device__ __forceinline__ void mma16816(float (&c)[4], const uint32_t (&a)[4],
                                         const uint32_t (&b)[2]) {
    asm volatile("mma.sync.aligned.m16n8k16.row.col.f32.bf16.bf16.f32 "
        "{%0,%1,%2,%3}, {%4,%5,%6,%7}, {%8,%9}, {%0,%1,%2,%3};"
        : "+f"(c[0]), "+f"(c[1]), "+f"(c[2]), "+f"(c[3])
        : "r"(a[0]), "r"(a[1]), "r"(a[2]), "r"(a[3]), "r"(b[0]), "r"(b[1]));
}
__device__ __forceinline__ uint32_t packbf(float lo, float hi) {
    uint32_t r;
    asm("cvt.rn.bf16x2.f32 %0, %1, %2;" : "=r"(r) : "f"(hi), "f"(lo));
    return r;
}
__device__ __forceinline__ float bf_round(float x) {
    return __bfloat162float(__float2bfloat16(x));
}
__device__ __forceinline__ void cvt4(uint2 &hi, uint2 &lo, float4 vv) {
    float v0 = vv.x, v1 = vv.y, v2 = vv.z, v3 = vv.w;
    __nv_bfloat16 h0 = __float2bfloat16(v0), h1 = __float2bfloat16(v1);
    __nv_bfloat16 h2 = __float2bfloat16(v2), h3 = __float2bfloat16(v3);
    __nv_bfloat162 hh0(h0, h1), hh1(h2, h3);
    __nv_bfloat162 ll0(__float2bfloat16(v0 - __bfloat162float(h0)),
                       __float2bfloat16(v1 - __bfloat162float(h1)));
    __nv_bfloat162 ll1(__float2bfloat16(v2 - __bfloat162float(h2)),
                       __float2bfloat16(v3 - __bfloat162float(h3)));
    hi = make_uint2(*(uint32_t*)&hh0, *(uint32_t*)&hh1);
    lo = make_uint2(*(uint32_t*)&ll0, *(uint32_t*)&ll1);
}

// ===========================================================================
// Split-bf16 tensor-core GEMM core — single barrier per K-chunk:
// LDG(c+1) -> COMPUTE(c) -> STS(c+1, other stage) -> syncthreads.
// ===========================================================================
#define PITCH 40
#define MAT_U (128*PITCH)
#define STAGE_U (4*MAT_U)
#define GT_SMEM (2*STAGE_U*2)

__device__ __forceinline__ size_t ymap(int m, int n, int mode) {
    if (mode == 0)
        return (((size_t)((m >> 11) * 16 + (n >> 6))) * 2048 + (m & 2047)) * 64 + (n & 63);
    return (size_t)m * 1024 + n;
}

__device__ __forceinline__ void gemm_core(
    const float* __restrict__ X, const float* __restrict__ W,
    float* __restrict__ Y, float scale, int mode, int bm, int bn,
    __nv_bfloat16* sh)
{
    const uint32_t sh0 = smem_u32(sh);
    const int t = threadIdx.x;
    const int warp = t >> 5, lane = t & 31;
    const int wm = (warp >> 1) * 32;
    const int wn = (warp & 1) * 64;
    const int lr = t >> 3, lc = (t & 7) * 4;

    float4 ra[4], rb[4];
    float acc[2][8][4];
    #pragma unroll
    for (int mt = 0; mt < 2; mt++)
        #pragma unroll
        for (int nt = 0; nt < 8; nt++)
            #pragma unroll
            for (int j = 0; j < 4; j++) acc[mt][nt][j] = 0.f;

    const int r8 = lane & 7, tl = lane >> 3;
    const uint32_t a_row = (uint32_t)(wm + (tl & 1) * 8 + r8);
    const uint32_t a_col = (uint32_t)((tl >> 1) * 16);
    const uint32_t b_row = (uint32_t)(wn + r8);
    const uint32_t b_col = (uint32_t)((tl & 1) * 16);

    #define GEMM_LDG(c) do {                                                     \
        const float* xp = X + (size_t)(bm + lr) * 1024 + (c) * 32 + lc;          \
        const float* wp = W + (size_t)(bn + lr) * 1024 + (c) * 32 + lc;          \
        _Pragma("unroll")                                                        \
        for (int p = 0; p < 4; p++) {                                            \
            ra[p] = *(const float4*)(xp + (size_t)p * 32 * 1024);                \
            rb[p] = *(const float4*)(wp + (size_t)p * 32 * 1024);                \
        }                                                                        \
    } while (0)

    #define GEMM_STS(s) do {                                                     \
        __nv_bfloat16* Ah = sh + (s) * STAGE_U;                                  \
        __nv_bfloat16* Al = Ah + MAT_U;                                          \
        __nv_bfloat16* Bh = Ah + 2 * MAT_U;                                      \
        __nv_bfloat16* Bl = Ah + 3 * MAT_U;                                      \
        _Pragma("unroll")                                                        \
        for (int p = 0; p < 4; p++) {                                            \
            int row = lr + p * 32;                                               \
            uint2 hi, lo;                                                        \
            cvt4(hi, lo, ra[p]);                                                 \
            *(uint2*)&Ah[row * PITCH + lc] = hi;                                 \
            *(uint2*)&Al[row * PITCH + lc] = lo;                                 \
            cvt4(hi, lo, rb[p]);                                                 \
            *(uint2*)&Bh[row * PITCH + lc] = hi;                                 \
            *(uint2*)&Bl[row * PITCH + lc] = lo;                                 \
        }                                                                        \
    } while (0)

    #define GEMM_COMPUTE(s) do {                                                 \
        uint32_t Ahi = sh0 + (s) * STAGE_U * 2;                                  \
        uint32_t Alo = Ahi + MAT_U * 2;                                          \
        uint32_t Bhi = Ahi + 2 * MAT_U * 2;                                      \
        uint32_t Blo = Ahi + 3 * MAT_U * 2;                                      \
        _Pragma("unroll")                                                        \
        for (int ks = 0; ks < 2; ks++) {                                         \
            uint32_t ah[2][4], al[2][4];                                         \
            _Pragma("unroll")                                                    \
            for (int mt = 0; mt < 2; mt++) {                                     \
                uint32_t off = (a_row + mt * 16) * 80 + a_col + ks * 32;         \
                ldsm_x4(ah[mt], Ahi + off);                                      \
                ldsm_x4(al[mt], Alo + off);                                      \
            }                                                                    \
            _Pragma("unroll")                                                    \
            for (int nt = 0; nt < 8; nt++) {                                     \
                uint32_t boff = (b_row + nt * 8) * 80 + b_col + ks * 32;         \
                uint32_t bh[2], bl[2];                                           \
                ldsm_x2(bh, Bhi + boff);                                         \
                ldsm_x2(bl, Blo + boff);                                         \
                _Pragma("unroll")                                                \
                for (int mt = 0; mt < 2; mt++) {                                 \
                    mma16816(acc[mt][nt], ah[mt], bh);                           \
                    mma16816(acc[mt][nt], ah[mt], bl);                           \
                    mma16816(acc[mt][nt], al[mt], bh);                           \
                }                                                                \
            }                                                                    \
        }                                                                        \
    } while (0)

    GEMM_LDG(0);
    GEMM_STS(0);
    __syncthreads();
    for (int c = 0; c < 32; c++) {
        if (c < 31) GEMM_LDG(c + 1);       // global loads for next chunk
        GEMM_COMPUTE(c & 1);               // MMAs on current stage
        if (c < 31) GEMM_STS((c + 1) & 1); // convert+store into OTHER stage
        __syncthreads();                   // single barrier per iteration
    }

    const int er = lane >> 2, ec = (lane & 3) * 2;
    #pragma unroll
    for (int mt = 0; mt < 2; mt++)
        #pragma unroll
        for (int nt = 0; nt < 8; nt++) {
            int m = bm + wm + mt * 16 + er;
            int n = bn + wn + nt * 8 + ec;
            float2 v0 = make_float2(acc[mt][nt][0] * scale, acc[mt][nt][1] * scale);
            float2 v1 = make_float2(acc[mt][nt][2] * scale, acc[mt][nt][3] * scale);
            *(float2*)&Y[ymap(m,     n, mode)] = v0;
            *(float2*)&Y[ymap(m + 8, n, mode)] = v1;
        }
}

// ---- merged Q/K/V projection: grid z selects input/weight/output ----------
__global__ __launch_bounds__(256) void qkv_gemm(
    const float* __restrict__ q, const float* __restrict__ k, const float* __restrict__ v,
    const float* __restrict__ wq, const float* __restrict__ wk, const float* __restrict__ wv,
    float* __restrict__ yq, float* __restrict__ yk, float* __restrict__ yv)
{
    extern __shared__ __nv_bfloat16 sh[];
    const int z = blockIdx.z;
    const float* X = z == 0 ? q : z == 1 ? k : v;
    const float* W = z == 0 ? wq : z == 1 ? wk : wv;
    float*       Y = z == 0 ? yq : z == 1 ? yk : yv;
    gemm_core(X, W, Y, z == 0 ? 0.125f : 1.0f, 0,
              blockIdx.y * 128, blockIdx.x * 128, sh);
}

// ---- W_O projection (own launch; runs concurrently with rescale) ----------
__global__ __launch_bounds__(256) void wo_gemm(
    const float* __restrict__ Ctx, const float* __restrict__ W_O,
    float* __restrict__ out)
{
    extern __shared__ __nv_bfloat16 sh[];
    gemm_core(Ctx, W_O, out, 1.0f, 1, blockIdx.y * 128, blockIdx.x * 128, sh);
}

// ---- rescale: zero smem, full occupancy, MLP-optimized (4 rows/iter) ------
__global__ __launch_bounds__(256) void rescale_kernel(
    float* __restrict__ attn, const float* __restrict__ L)
{
    const int t = threadIdx.x;
    const int row0 = blockIdx.x * 32;
    float4* base = (float4*)(attn + (size_t)row0 * 2048);
    #pragma unroll 1
    for (int g = 0; g < 8; g++) {
        float inv0 = 1.0f / L[row0 + g*4 + 0];
        float inv1 = 1.0f / L[row0 + g*4 + 1];
        float inv2 = 1.0f / L[row0 + g*4 + 2];
        float inv3 = 1.0f / L[row0 + g*4 + 3];
        float4* p0 = base + (size_t)(g*4 + 0) * 512;
        float4* p1 = base + (size_t)(g*4 + 1) * 512;
        float4* p2 = base + (size_t)(g*4 + 2) * 512;
        float4* p3 = base + (size_t)(g*4 + 3) * 512;
        float4 a0 = p0[t], b0 = p0[t + 256];
        float4 a1 = p1[t], b1 = p1[t + 256];
        float4 a2 = p2[t], b2 = p2[t + 256];
        float4 a3 = p3[t], b3 = p3[t + 256];
        a0.x *= inv0; a0.y *= inv0; a0.z *= inv0; a0.w *= inv0;
        b0.x *= inv0; b0.y *= inv0; b0.z *= inv0; b0.w *= inv0;
        a1.x *= inv1; a1.y *= inv1; a1.z *= inv1; a1.w *= inv1;
        b1.x *= inv1; b1.y *= inv1; b1.z *= inv1; b1.w *= inv1;
        a2.x *= inv2; a2.y *= inv2; a2.z *= inv2; a2.w *= inv2;
        b2.x *= inv2; b2.y *= inv2; b2.z *= inv2; b2.w *= inv2;
        a3.x *= inv3; a3.y *= inv3; a3.z *= inv3; a3.w *= inv3;
        b3.x *= inv3; b3.y *= inv3; b3.z *= inv3; b3.w *= inv3;
        p0[t] = a0; p0[t + 256] = b0;
        p1[t] = a1; p1[t + 256] = b1;
        p2[t] = a2; p2[t + 256] = b2;
        p3[t] = a3; p3[t + 256] = b3;
    }
}

// ===========================================================================
// Tensor-core attention (R12-exact, 380us): Q-fragment hoisting +
// double-buffered K/V stages with register prefetch, one barrier/iter.
// ===========================================================================
#define APB 144                        /* bytes per 72-bf16 row */
#define AQHI 0
#define AQLO 18432
#define ASKV 36864                     /* K/V stages base */
#define ASTG 36864                     /* per-stage: Khi,Klo,Vhi,Vlo x 9216 */
#define ALP  (ASKV + 2*ASTG)           /* 110592: 256 f32 partials */
#define AMSK (ALP + 1024)              /* 111616: 2 x 64 ints */
#define AT_SMEM (AMSK + 512)           /* 112128 */

__global__ __launch_bounds__(256, 1) void attn_mma(
    const float* __restrict__ Qh, const float* __restrict__ Kh,
    const float* __restrict__ Vh, const int* __restrict__ mask,
    float* __restrict__ attn, float* __restrict__ Ctx, float* __restrict__ Lout)
{
    extern __shared__ char ash[];
    const uint32_t s0 = smem_u32(ash);
    float* Lpart = (float*)(ash + ALP);
    int*   Msk   = (int*)(ash + AMSK);

    const int t = threadIdx.x, warp = t >> 5, lane = t & 31;
    const int qw = warp >> 1, kw = warp & 1;
    const int q0 = blockIdx.x * 128, h = blockIdx.y, b = blockIdx.z;
    const int bh = b * H_ + h;
    const float* Qb = Qh + (size_t)bh * S_ * 64;
    const float* Kb = Kh + (size_t)bh * S_ * 64;
    const float* Vb = Vh + (size_t)bh * S_ * 64;

    Lpart[t] = 0.f;

    const int lr = t >> 3, lc = (t & 7) * 8;

    // ---- load Q tile (128x64) -> Qhi/Qlo smem ----
    #pragma unroll
    for (int p = 0; p < 4; p++) {
        int row = lr + 32 * p;
        const float* src = Qb + (size_t)(q0 + row) * 64 + lc;
        uint2 hi, lo;
        cvt4(hi, lo, *(const float4*)src);
        *(uint2*)(ash + AQHI + row * APB + lc * 2)     = hi;
        *(uint2*)(ash + AQLO + row * APB + lc * 2)     = lo;
        cvt4(hi, lo, *(const float4*)(src + 4));
        *(uint2*)(ash + AQHI + row * APB + lc * 2 + 8) = hi;
        *(uint2*)(ash + AQLO + row * APB + lc * 2 + 8) = lo;
    }

    const int r8 = lane & 7, tl = lane >> 3;
    const int er = lane >> 2, ec = (lane & 3) * 2;
    const uint32_t a_roff = (uint32_t)((qw * 32 + (tl & 1) * 8 + r8) * APB + (tl >> 1) * 16);
    const uint32_t b_roff = (uint32_t)((kw * 32 + r8) * APB + (tl & 1) * 16);
    const uint32_t v_roff = (uint32_t)((kw * 32 + (tl & 1) * 8 + r8) * APB);

    // ---- prefetch registers + macros ----
    float4 fk[4], fv[4];
    int pm = 0;

    #define AT_LDG(c) do {                                                       \
        int kb_ = (c) * 64;                                                      \
        const float* sk0 = Kb + (size_t)(kb_ + lr) * 64 + lc;                    \
        const float* sv0 = Vb + (size_t)(kb_ + lr) * 64 + lc;                    \
        fk[0] = *(const float4*)sk0;           fk[1] = *(const float4*)(sk0 + 4);\
        fk[2] = *(const float4*)(sk0 + 32*64); fk[3] = *(const float4*)(sk0 + 32*64 + 4); \
        fv[0] = *(const float4*)sv0;           fv[1] = *(const float4*)(sv0 + 4);\
        fv[2] = *(const float4*)(sv0 + 32*64); fv[3] = *(const float4*)(sv0 + 32*64 + 4); \
        if (t < 64) pm = mask[b * S_ + kb_ + t];                                 \
    } while (0)

    #define AT_STS(st) do {                                                      \
        char* kh_b = ash + ASKV + (st) * ASTG;                                   \
        _Pragma("unroll")                                                        \
        for (int p = 0; p < 2; p++) {                                            \
            int row = lr + 32 * p;                                               \
            uint2 hi, lo;                                                        \
            cvt4(hi, lo, fk[2*p]);                                               \
            *(uint2*)(kh_b + row * APB + lc * 2)              = hi;              \
            *(uint2*)(kh_b + 9216 + row * APB + lc * 2)       = lo;              \
            cvt4(hi, lo, fk[2*p + 1]);                                           \
            *(uint2*)(kh_b + row * APB + lc * 2 + 8)          = hi;              \
            *(uint2*)(kh_b + 9216 + row * APB + lc * 2 + 8)   = lo;              \
            cvt4(hi, lo, fv[2*p]);                                               \
            *(uint2*)(kh_b + 18432 + row * APB + lc * 2)      = hi;              \
            *(uint2*)(kh_b + 27648 + row * APB + lc * 2)      = lo;              \
            cvt4(hi, lo, fv[2*p + 1]);                                           \
            *(uint2*)(kh_b + 18432 + row * APB + lc * 2 + 8)  = hi;              \
            *(uint2*)(kh_b + 27648 + row * APB + lc * 2 + 8)  = lo;              \
        }                                                                        \
        if (t < 64) Msk[(st) * 64 + t] = pm;                                     \
    } while (0)

    // prologue: stage 0 filled, Q visible
    AT_LDG(0);
    __syncthreads();                   // Q smem writes visible for hoist

    // ---- hoist Q fragments into registers (chunk-invariant) ----
    uint32_t qh_r[2][4][4], ql_r[2][4][4];   // [mt][ks][frag]
    #pragma unroll
    for (int mt = 0; mt < 2; mt++)
        #pragma unroll
        for (int ks = 0; ks < 4; ks++) {
            uint32_t off = a_roff + mt * 16 * APB + ks * 32;
            ldsm_x4(qh_r[mt][ks], s0 + AQHI + off);
            ldsm_x4(ql_r[mt][ks], s0 + AQLO + off);
        }

    AT_STS(0);
    __syncthreads();

    float oacc[2][8][4];
    #pragma unroll
    for (int mt = 0; mt < 2; mt++)
        #pragma unroll
        for (int nt = 0; nt < 8; nt++)
            #pragma unroll
            for (int j = 0; j < 4; j++) oacc[mt][nt][j] = 0.f;

    for (int c = 0; c < 32; c++) {
        const int kb = c * 64;
        const int st = c & 1;
        const uint32_t sKh = s0 + ASKV + st * ASTG;
        const uint32_t sKl = sKh + 9216;
        const uint32_t sVh = sKh + 18432;
        const uint32_t sVl = sKh + 27648;

        if (c < 31) AT_LDG(c + 1);     // issue next chunk's loads now

        // ---- S = Q K^T (32q x 32k per warp), Q frags from registers ----
        float sc[2][4][4];
        #pragma unroll
        for (int mt = 0; mt < 2; mt++)
            #pragma unroll
            for (int nf = 0; nf < 4; nf++)
                #pragma unroll
                for (int j = 0; j < 4; j++) sc[mt][nf][j] = 0.f;

        #pragma unroll
        for (int ks = 0; ks < 4; ks++) {
            #pragma unroll
            for (int nf = 0; nf < 4; nf++) {
                uint32_t boff = b_roff + nf * 8 * APB + ks * 32;
                uint32_t kh_[2], kl_[2];
                ldsm_x2(kh_, sKh + boff);
                ldsm_x2(kl_, sKl + boff);
                #pragma unroll
                for (int mt = 0; mt < 2; mt++) {
                    mma16816(sc[mt][nf], qh_r[mt][ks], kh_);
                    mma16816(sc[mt][nf], qh_r[mt][ks], kl_);
                    mma16816(sc[mt][nf], ql_r[mt][ks], kh_);
                }
            }
        }

        // ---- epilogue: mask+exp, row sums, attn store, P frags ----
        uint32_t phi[2][2][4], plo[2][2][4];
        #pragma unroll
        for (int mt = 0; mt < 2; mt++) {
            float rs0 = 0.f, rs1 = 0.f;
            #pragma unroll
            for (int nf = 0; nf < 4; nf++) {
                int col = kw * 32 + nf * 8 + ec;
                int m0 = Msk[st * 64 + col], m1 = Msk[st * 64 + col + 1];
                float p00 = m0 ? __expf(sc[mt][nf][0]) : 0.f;
                float p01 = m1 ? __expf(sc[mt][nf][1]) : 0.f;
                float p10 = m0 ? __expf(sc[mt][nf][2]) : 0.f;
                float p11 = m1 ? __expf(sc[mt][nf][3]) : 0.f;
                rs0 += p00 + p01; rs1 += p10 + p11;
                if (attn) {
                    int q = q0 + qw * 32 + mt * 16 + er;
                    size_t ro = ((size_t)bh * S_ + q) * S_ + kb + col;
                    *(float2*)&attn[ro]          = make_float2(p00, p01);
                    *(float2*)&attn[ro + 8 * S_] = make_float2(p10, p11);
                }
                int kf = nf >> 1, hf = (nf & 1) * 2;
                float h00 = bf_round(p00), h01 = bf_round(p01);
                float h10 = bf_round(p10), h11 = bf_round(p11);
                phi[mt][kf][hf]     = packbf(h00, h01);
                phi[mt][kf][hf + 1] = packbf(h10, h11);
                plo[mt][kf][hf]     = packbf(p00 - h00, p01 - h01);
                plo[mt][kf][hf + 1] = packbf(p10 - h10, p11 - h11);
            }
            rs0 += __shfl_xor_sync(0xffffffffu, rs0, 1);
            rs0 += __shfl_xor_sync(0xffffffffu, rs0, 2);
            rs1 += __shfl_xor_sync(0xffffffffu, rs1, 1);
            rs1 += __shfl_xor_sync(0xffffffffu, rs1, 2);
            if ((lane & 3) == 0) {
                int q = qw * 32 + mt * 16 + er;
                Lpart[kw * 128 + q]     += rs0;
                Lpart[kw * 128 + q + 8] += rs1;
            }
        }

        // ---- O += P V (keys slice of this warp), split 3-term ----
        #pragma unroll
        for (int kf = 0; kf < 2; kf++) {
            #pragma unroll
            for (int nf2 = 0; nf2 < 8; nf2++) {
                uint32_t voff = v_roff + kf * 16 * APB + nf2 * 16;
                uint32_t vh_[2], vl_[2];
                ldsm_x2t(vh_, sVh + voff);
                ldsm_x2t(vl_, sVl + voff);
                #pragma unroll
                for (int mt = 0; mt < 2; mt++) {
                    mma16816(oacc[mt][nf2], phi[mt][kf], vh_);
                    mma16816(oacc[mt][nf2], phi[mt][kf], vl_);
                    mma16816(oacc[mt][nf2], plo[mt][kf], vh_);
                }
            }
        }

        // ---- store prefetched chunk into the OTHER stage, one barrier ----
        if (c < 31) AT_STS((c + 1) & 1);
        __syncthreads();
    }

    // ---- reduce O across the 2 k-warps via smem, normalize, write ----
    float* Ored = (float*)(ash + ASKV);        // reuse stage area
    if (kw == 1) {
        #pragma unroll
        for (int mt = 0; mt < 2; mt++)
            #pragma unroll
            for (int nf2 = 0; nf2 < 8; nf2++) {
                int q = qw * 32 + mt * 16 + er, d = nf2 * 8 + ec;
                *(float2*)&Ored[q * 68 + d]       = make_float2(oacc[mt][nf2][0], oacc[mt][nf2][1]);
                *(float2*)&Ored[(q + 8) * 68 + d] = make_float2(oacc[mt][nf2][2], oacc[mt][nf2][3]);
            }
    }
    __syncthreads();
    if (kw == 0) {
        #pragma unroll
        for (int mt = 0; mt < 2; mt++) {
            int qA = qw * 32 + mt * 16 + er;
            float invA = 1.f / (Lpart[qA] + Lpart[128 + qA]);
            float invB = 1.f / (Lpart[qA + 8] + Lpart[128 + qA + 8]);
            #pragma unroll
            for (int nf2 = 0; nf2 < 8; nf2++) {
                int d = nf2 * 8 + ec;
                float2 oA = *(float2*)&Ored[qA * 68 + d];
                float2 oB = *(float2*)&Ored[(qA + 8) * 68 + d];
                oA.x = (oA.x + oacc[mt][nf2][0]) * invA;
                oA.y = (oA.y + oacc[mt][nf2][1]) * invA;
                oB.x = (oB.x + oacc[mt][nf2][2]) * invB;
                oB.y = (oB.y + oacc[mt][nf2][3]) * invB;
                size_t oo = ((size_t)b * S_ + q0 + qA) * D_ + h * 64 + d;
                *(float2*)&Ctx[oo]          = oA;
                *(float2*)&Ctx[oo + 8 * D_] = oB;
            }
        }
    }
    if (t < 128) Lout[(size_t)bh * S_ + q0 + t] = Lpart[t] + Lpart[128 + t];
}

// ===========================================================================
extern "C" void kernel_launch(void* const* d_in, const int* in_sizes, int n_in,
                              void* d_out, int out_size)
{
    const float* query = (const float*)d_in[0];
    const float* key   = (const float*)d_in[1];
    const float* value = (const float*)d_in[2];
    const int*   mask  = (const int*)d_in[3];
    const float* W_Q   = (const float*)d_in[4];
    const float* W_K   = (const float*)d_in[5];
    const float* W_V   = (const float*)d_in[6];
    const float* W_O   = (const float*)d_in[7];

    float* out = (float*)d_out;
    bool hasAttn = (out_size >= OUT_ELEMS + ATT_ELEMS);
    float* attn = hasAttn ? (out + OUT_ELEMS) : nullptr;

    float *gq, *gk, *gv, *gc, *gl;
    cudaGetSymbolAddress((void**)&gq, g_Q);
    cudaGetSymbolAddress((void**)&gk, g_K);
    cudaGetSymbolAddress((void**)&gv, g_V);
    cudaGetSymbolAddress((void**)&gc, g_C);
    cudaGetSymbolAddress((void**)&gl, g_L);

    static cudaStream_t s2 = nullptr;
    static cudaEvent_t evFork = nullptr, evJoin = nullptr;
    if (s2 == nullptr) {
        cudaStreamCreateWithFlags(&s2, cudaStreamNonBlocking);
        cudaEventCreateWithFlags(&evFork, cudaEventDisableTiming);
        cudaEventCreateWithFlags(&evJoin, cudaEventDisableTiming);
        cudaFuncSetAttribute((const void*)attn_mma,
                             cudaFuncAttributeMaxDynamicSharedMemorySize, AT_SMEM);
        cudaFuncSetAttribute((const void*)qkv_gemm,
                             cudaFuncAttributeMaxDynamicSharedMemorySize, GT_SMEM);
        cudaFuncSetAttribute((const void*)wo_gemm,
                             cudaFuncAttributeMaxDynamicSharedMemorySize, GT_SMEM);
    }

    qkv_gemm<<<dim3(8, 32, 3), 256, GT_SMEM>>>(query, key, value,
                                               W_Q, W_K, W_V, gq, gk, gv);
    attn_mma<<<dim3(16, 16, 2), 256, AT_SMEM>>>(gq, gk, gv, mask, attn, gc, gl);

    if (hasAttn) {
        // fork: rescale (DRAM-bound) on s2, W_O GEMM (tensor-bound) on main
        cudaEventRecord(evFork, 0);
        cudaStreamWaitEvent(s2, evFork, 0);
        rescale_kernel<<<2048, 256, 0, s2>>>(attn, gl);
        wo_gemm<<<dim3(8, 32), 256, GT_SMEM>>>(gc, W_O, out);
        cudaEventRecord(evJoin, s2);
        cudaStreamWaitEvent((cudaStream_t)0, evJoin, 0);
    } else {
        wo_gemm<<<dim3(8, 32), 256, GT_SMEM>>>(gc, W_O, out);
    }
}

// round 15
// speedup vs baseline: 1.3504x; 1.0141x over previous
#include <cuda_runtime.h>
#include <cuda_bf16.h>
#include <cstdint>

#define B_ 2
#define S_ 2048
#define D_ 1024
#define H_ 16
#define DK_ 64
#define OUT_ELEMS (B_*S_*D_)           /* 4194304  */
#define ATT_ELEMS (B_*H_*S_*S_)        /* 134217728 */

// ---------------- scratch (device globals; no allocation allowed) ----------
__device__ float g_Q[B_*H_*S_*DK_];    // [b][h][s][d], pre-scaled by 1/8
__device__ float g_K[B_*H_*S_*DK_];
__device__ float g_V[B_*H_*S_*DK_];
__device__ float g_C[B_*S_*D_];        // context, token-major
__device__ float g_L[B_*H_*S_];        // softmax row sums

__device__ __forceinline__ uint32_t smem_u32(const void* p) {
    uint32_t a;
    asm("{ .reg .u64 t; cvta.to.shared.u64 t, %1; cvt.u32.u64 %0, t; }" : "=r"(a) : "l"(p));
    return a;
}

// ---------------- mma.sync primitives (baseline PTX, no 'a' features) ------
__device__ __forceinline__ void ldsm_x4(uint32_t (&r)[4], uint32_t addr) {
    asm volatile("ldmatrix.sync.aligned.m8n8.x4.shared.b16 {%0,%1,%2,%3}, [%4];"
        : "=r"(r[0]), "=r"(r[1]), "=r"(r[2]), "=r"(r[3]) : "r"(addr));
}
__device__ __forceinline__ void ldsm_x4t(uint32_t (&r)[4], uint32_t addr) {
    asm volatile("ldmatrix.sync.aligned.m8n8.x4.trans.shared.b16 {%0,%1,%2,%3}, [%4];"
        : "=r"(r[0]), "=r"(r[1]), "=r"(r[2]), "=r"(r[3]) : "r"(addr));
}
__device__ __forceinline__ void mma16816(float (&c)[4], const uint32_t (&a)[4],
                                         const uint32_t* b) {
    asm volatile("mma.sync.aligned.m16n8k16.row.col.f32.bf16.bf16.f32 "
        "{%0,%1,%2,%3}, {%4,%5,%6,%7}, {%8,%9}, {%0,%1,%2,%3};"
        : "+f"(c[0]), "+f"(c[1]), "+f"(c[2]), "+f"(c[3])
        : "r"(a[0]), "r"(a[1]), "r"(a[2]), "r"(a[3]), "r"(b[0]), "r"(b[1]));
}
__device__ __forceinline__ uint32_t packbf(float lo, float hi) {
    uint32_t r;
    asm("cvt.rn.bf16x2.f32 %0, %1, %2;" : "=r"(r) : "f"(hi), "f"(lo));
    return r;
}
__device__ __forceinline__ float bf_round(float x) {
    return __bfloat162float(__float2bfloat16(x));
}
__device__ __forceinline__ void cvt4(uint2 &hi, uint2 &lo, float4 vv) {
    float v0 = vv.x, v1 = vv.y, v2 = vv.z, v3 = vv.w;
    __nv_bfloat16 h0 = __float2bfloat16(v0), h1 = __float2bfloat16(v1);
    __nv_bfloat16 h2 = __float2bfloat16(v2), h3 = __float2bfloat16(v3);
    __nv_bfloat162 hh0(h0, h1), hh1(h2, h3);
    __nv_bfloat162 ll0(__float2bfloat16(v0 - __bfloat162float(h0)),
                       __float2bfloat16(v1 - __bfloat162float(h1)));
    __nv_bfloat162 ll1(__float2bfloat16(v2 - __bfloat162float(h2)),
                       __float2bfloat16(v3 - __bfloat162float(h3)));
    hi = make_uint2(*(uint32_t*)&hh0, *(uint32_t*)&hh1);
    lo = make_uint2(*(uint32_t*)&ll0, *(uint32_t*)&ll1);
}

// ===========================================================================
// Split-bf16 tensor-core GEMM core — single barrier per K-chunk, x4-paired
// B-fragment loads (one ldsm_x4 feeds two n-tiles).
// ===========================================================================
#define PITCH 40
#define MAT_U (128*PITCH)
#define STAGE_U (4*MAT_U)
#define GT_SMEM (2*STAGE_U*2)

__device__ __forceinline__ size_t ymap(int m, int n, int mode) {
    if (mode == 0)
        return (((size_t)((m >> 11) * 16 + (n >> 6))) * 2048 + (m & 2047)) * 64 + (n & 63);
    return (size_t)m * 1024 + n;
}

__device__ __forceinline__ void gemm_core(
    const float* __restrict__ X, const float* __restrict__ W,
    float* __restrict__ Y, float scale, int mode, int bm, int bn,
    __nv_bfloat16* sh)
{
    const uint32_t sh0 = smem_u32(sh);
    const int t = threadIdx.x;
    const int warp = t >> 5, lane = t & 31;
    const int wm = (warp >> 1) * 32;
    const int wn = (warp & 1) * 64;
    const int lr = t >> 3, lc = (t & 7) * 4;

    float4 ra[4], rb[4];
    float acc[2][8][4];
    #pragma unroll
    for (int mt = 0; mt < 2; mt++)
        #pragma unroll
        for (int nt = 0; nt < 8; nt++)
            #pragma unroll
            for (int j = 0; j < 4; j++) acc[mt][nt][j] = 0.f;

    const int r8 = lane & 7, tl = lane >> 3;
    const uint32_t a_row = (uint32_t)(wm + (tl & 1) * 8 + r8);
    const uint32_t a_col = (uint32_t)((tl >> 1) * 16);
    // x4-paired B: lane groups 0,1 -> n-tile rows; groups 2,3 -> n+8 rows
    const uint32_t b_row4 = (uint32_t)(wn + (tl >> 1) * 8 + r8);
    const uint32_t b_col4 = (uint32_t)((tl & 1) * 16);

    #define GEMM_LDG(c) do {                                                     \
        const float* xp = X + (size_t)(bm + lr) * 1024 + (c) * 32 + lc;          \
        const float* wp = W + (size_t)(bn + lr) * 1024 + (c) * 32 + lc;          \
        _Pragma("unroll")                                                        \
        for (int p = 0; p < 4; p++) {                                            \
            ra[p] = *(const float4*)(xp + (size_t)p * 32 * 1024);                \
            rb[p] = *(const float4*)(wp + (size_t)p * 32 * 1024);                \
        }                                                                        \
    } while (0)

    #define GEMM_STS(s) do {                                                     \
        __nv_bfloat16* Ah = sh + (s) * STAGE_U;                                  \
        __nv_bfloat16* Al = Ah + MAT_U;                                          \
        __nv_bfloat16* Bh = Ah + 2 * MAT_U;                                      \
        __nv_bfloat16* Bl = Ah + 3 * MAT_U;                                      \
        _Pragma("unroll")                                                        \
        for (int p = 0; p < 4; p++) {                                            \
            int row = lr + p * 32;                                               \
            uint2 hi, lo;                                                        \
            cvt4(hi, lo, ra[p]);                                                 \
            *(uint2*)&Ah[row * PITCH + lc] = hi;                                 \
            *(uint2*)&Al[row * PITCH + lc] = lo;                                 \
            cvt4(hi, lo, rb[p]);                                                 \
            *(uint2*)&Bh[row * PITCH + lc] = hi;                                 \
            *(uint2*)&Bl[row * PITCH + lc] = lo;                                 \
        }                                                                        \
    } while (0)

    #define GEMM_COMPUTE(s) do {                                                 \
        uint32_t Ahi = sh0 + (s) * STAGE_U * 2;                                  \
        uint32_t Alo = Ahi + MAT_U * 2;                                          \
        uint32_t Bhi = Ahi + 2 * MAT_U * 2;                                      \
        uint32_t Blo = Ahi + 3 * MAT_U * 2;                                      \
        _Pragma("unroll")                                                        \
        for (int ks = 0; ks < 2; ks++) {                                         \
            uint32_t ah[2][4], al[2][4];                                         \
            _Pragma("unroll")                                                    \
            for (int mt = 0; mt < 2; mt++) {                                     \
                uint32_t off = (a_row + mt * 16) * 80 + a_col + ks * 32;         \
                ldsm_x4(ah[mt], Ahi + off);                                      \
                ldsm_x4(al[mt], Alo + off);                                      \
            }                                                                    \
            _Pragma("unroll")                                                    \
            for (int np = 0; np < 4; np++) {                                     \
                uint32_t boff = (b_row4 + np * 16) * 80 + b_col4 + ks * 32;      \
                uint32_t bh4[4], bl4[4];                                         \
                ldsm_x4(bh4, Bhi + boff);                                        \
                ldsm_x4(bl4, Blo + boff);                                        \
                _Pragma("unroll")                                                \
                for (int hh = 0; hh < 2; hh++) {                                 \
                    int nt = np * 2 + hh;                                        \
                    _Pragma("unroll")                                            \
                    for (int mt = 0; mt < 2; mt++) {                             \
                        mma16816(acc[mt][nt], ah[mt], &bh4[hh * 2]);             \
                        mma16816(acc[mt][nt], ah[mt], &bl4[hh * 2]);             \
                        mma16816(acc[mt][nt], al[mt], &bh4[hh * 2]);             \
                    }                                                            \
                }                                                                \
            }                                                                    \
        }                                                                        \
    } while (0)

    GEMM_LDG(0);
    GEMM_STS(0);
    __syncthreads();
    for (int c = 0; c < 32; c++) {
        if (c < 31) GEMM_LDG(c + 1);
        GEMM_COMPUTE(c & 1);
        if (c < 31) GEMM_STS((c + 1) & 1);
        __syncthreads();
    }

    const int er = lane >> 2, ec = (lane & 3) * 2;
    #pragma unroll
    for (int mt = 0; mt < 2; mt++)
        #pragma unroll
        for (int nt = 0; nt < 8; nt++) {
            int m = bm + wm + mt * 16 + er;
            int n = bn + wn + nt * 8 + ec;
            float2 v0 = make_float2(acc[mt][nt][0] * scale, acc[mt][nt][1] * scale);
            float2 v1 = make_float2(acc[mt][nt][2] * scale, acc[mt][nt][3] * scale);
            *(float2*)&Y[ymap(m,     n, mode)] = v0;
            *(float2*)&Y[ymap(m + 8, n, mode)] = v1;
        }
}

// ---- merged Q/K/V projection: grid z selects input/weight/output ----------
__global__ __launch_bounds__(256) void qkv_gemm(
    const float* __restrict__ q, const float* __restrict__ k, const float* __restrict__ v,
    const float* __restrict__ wq, const float* __restrict__ wk, const float* __restrict__ wv,
    float* __restrict__ yq, float* __restrict__ yk, float* __restrict__ yv)
{
    extern __shared__ __nv_bfloat16 sh[];
    const int z = blockIdx.z;
    const float* X = z == 0 ? q : z == 1 ? k : v;
    const float* W = z == 0 ? wq : z == 1 ? wk : wv;
    float*       Y = z == 0 ? yq : z == 1 ? yk : yv;
    gemm_core(X, W, Y, z == 0 ? 0.125f : 1.0f, 0,
              blockIdx.y * 128, blockIdx.x * 128, sh);
}

// ---- W_O projection (own launch; runs concurrently with rescale) ----------
__global__ __launch_bounds__(256) void wo_gemm(
    const float* __restrict__ Ctx, const float* __restrict__ W_O,
    float* __restrict__ out)
{
    extern __shared__ __nv_bfloat16 sh[];
    gemm_core(Ctx, W_O, out, 1.0f, 1, blockIdx.y * 128, blockIdx.x * 128, sh);
}

// ---- rescale: zero smem, full occupancy, MLP-optimized (4 rows/iter) ------
__global__ __launch_bounds__(256) void rescale_kernel(
    float* __restrict__ attn, const float* __restrict__ L)
{
    const int t = threadIdx.x;
    const int row0 = blockIdx.x * 32;
    float4* base = (float4*)(attn + (size_t)row0 * 2048);
    #pragma unroll 1
    for (int g = 0; g < 8; g++) {
        float inv0 = 1.0f / L[row0 + g*4 + 0];
        float inv1 = 1.0f / L[row0 + g*4 + 1];
        float inv2 = 1.0f / L[row0 + g*4 + 2];
        float inv3 = 1.0f / L[row0 + g*4 + 3];
        float4* p0 = base + (size_t)(g*4 + 0) * 512;
        float4* p1 = base + (size_t)(g*4 + 1) * 512;
        float4* p2 = base + (size_t)(g*4 + 2) * 512;
        float4* p3 = base + (size_t)(g*4 + 3) * 512;
        float4 a0 = p0[t], b0 = p0[t + 256];
        float4 a1 = p1[t], b1 = p1[t + 256];
        float4 a2 = p2[t], b2 = p2[t + 256];
        float4 a3 = p3[t], b3 = p3[t + 256];
        a0.x *= inv0; a0.y *= inv0; a0.z *= inv0; a0.w *= inv0;
        b0.x *= inv0; b0.y *= inv0; b0.z *= inv0; b0.w *= inv0;
        a1.x *= inv1; a1.y *= inv1; a1.z *= inv1; a1.w *= inv1;
        b1.x *= inv1; b1.y *= inv1; b1.z *= inv1; b1.w *= inv1;
        a2.x *= inv2; a2.y *= inv2; a2.z *= inv2; a2.w *= inv2;
        b2.x *= inv2; b2.y *= inv2; b2.z *= inv2; b2.w *= inv2;
        a3.x *= inv3; a3.y *= inv3; a3.z *= inv3; a3.w *= inv3;
        b3.x *= inv3; b3.y *= inv3; b3.z *= inv3; b3.w *= inv3;
        p0[t] = a0; p0[t + 256] = b0;
        p1[t] = a1; p1[t + 256] = b1;
        p2[t] = a2; p2[t + 256] = b2;
        p3[t] = a3; p3[t + 256] = b3;
    }
}

// ===========================================================================
// Tensor-core attention: Q-fragment hoisting + double-buffered K/V stages +
// x4-paired K/V fragment loads.
// ===========================================================================
#define APB 144                        /* bytes per 72-bf16 row */
#define AQHI 0
#define AQLO 18432
#define ASKV 36864                     /* K/V stages base */
#define ASTG 36864                     /* per-stage: Khi,Klo,Vhi,Vlo x 9216 */
#define ALP  (ASKV + 2*ASTG)           /* 110592: 256 f32 partials */
#define AMSK (ALP + 1024)              /* 111616: 2 x 64 ints */
#define AT_SMEM (AMSK + 512)           /* 112128 */

__global__ __launch_bounds__(256, 1) void attn_mma(
    const float* __restrict__ Qh, const float* __restrict__ Kh,
    const float* __restrict__ Vh, const int* __restrict__ mask,
    float* __restrict__ attn, float* __restrict__ Ctx, float* __restrict__ Lout)
{
    extern __shared__ char ash[];
    const uint32_t s0 = smem_u32(ash);
    float* Lpart = (float*)(ash + ALP);
    int*   Msk   = (int*)(ash + AMSK);

    const int t = threadIdx.x, warp = t >> 5, lane = t & 31;
    const int qw = warp >> 1, kw = warp & 1;
    const int q0 = blockIdx.x * 128, h = blockIdx.y, b = blockIdx.z;
    const int bh = b * H_ + h;
    const float* Qb = Qh + (size_t)bh * S_ * 64;
    const float* Kb = Kh + (size_t)bh * S_ * 64;
    const float* Vb = Vh + (size_t)bh * S_ * 64;

    Lpart[t] = 0.f;

    const int lr = t >> 3, lc = (t & 7) * 8;

    // ---- load Q tile (128x64) -> Qhi/Qlo smem ----
    #pragma unroll
    for (int p = 0; p < 4; p++) {
        int row = lr + 32 * p;
        const float* src = Qb + (size_t)(q0 + row) * 64 + lc;
        uint2 hi, lo;
        cvt4(hi, lo, *(const float4*)src);
        *(uint2*)(ash + AQHI + row * APB + lc * 2)     = hi;
        *(uint2*)(ash + AQLO + row * APB + lc * 2)     = lo;
        cvt4(hi, lo, *(const float4*)(src + 4));
        *(uint2*)(ash + AQHI + row * APB + lc * 2 + 8) = hi;
        *(uint2*)(ash + AQLO + row * APB + lc * 2 + 8) = lo;
    }

    const int r8 = lane & 7, tl = lane >> 3;
    const int er = lane >> 2, ec = (lane & 3) * 2;
    const uint32_t a_roff = (uint32_t)((qw * 32 + (tl & 1) * 8 + r8) * APB + (tl >> 1) * 16);
    // x4-paired K: groups 0,1 -> n-tile; groups 2,3 -> n+8
    const uint32_t b_roff4 = (uint32_t)((kw * 32 + (tl >> 1) * 8 + r8) * APB + (tl & 1) * 16);
    // x4-paired V (trans): groups 0,1 -> k halves of d-tile; groups 2,3 -> d+8
    const uint32_t v_roff4 = (uint32_t)((kw * 32 + (tl & 1) * 8 + r8) * APB + (tl >> 1) * 16);

    // ---- prefetch registers + macros ----
    float4 fk[4], fv[4];
    int pm = 0;

    #define AT_LDG(c) do {                                                       \
        int kb_ = (c) * 64;                                                      \
        const float* sk0 = Kb + (size_t)(kb_ + lr) * 64 + lc;                    \
        const float* sv0 = Vb + (size_t)(kb_ + lr) * 64 + lc;                    \
        fk[0] = *(const float4*)sk0;           fk[1] = *(const float4*)(sk0 + 4);\
        fk[2] = *(const float4*)(sk0 + 32*64); fk[3] = *(const float4*)(sk0 + 32*64 + 4); \
        fv[0] = *(const float4*)sv0;           fv[1] = *(const float4*)(sv0 + 4);\
        fv[2] = *(const float4*)(sv0 + 32*64); fv[3] = *(const float4*)(sv0 + 32*64 + 4); \
        if (t < 64) pm = mask[b * S_ + kb_ + t];                                 \
    } while (0)

    #define AT_STS(st) do {                                                      \
        char* kh_b = ash + ASKV + (st) * ASTG;                                   \
        _Pragma("unroll")                                                        \
        for (int p = 0; p < 2; p++) {                                            \
            int row = lr + 32 * p;                                               \
            uint2 hi, lo;                                                        \
            cvt4(hi, lo, fk[2*p]);                                               \
            *(uint2*)(kh_b + row * APB + lc * 2)              = hi;              \
            *(uint2*)(kh_b + 9216 + row * APB + lc * 2)       = lo;              \
            cvt4(hi, lo, fk[2*p + 1]);                                           \
            *(uint2*)(kh_b + row * APB + lc * 2 + 8)          = hi;              \
            *(uint2*)(kh_b + 9216 + row * APB + lc * 2 + 8)   = lo;              \
            cvt4(hi, lo, fv[2*p]);                                               \
            *(uint2*)(kh_b + 18432 + row * APB + lc * 2)      = hi;              \
            *(uint2*)(kh_b + 27648 + row * APB + lc * 2)      = lo;              \
            cvt4(hi, lo, fv[2*p + 1]);                                           \
            *(uint2*)(kh_b + 18432 + row * APB + lc * 2 + 8)  = hi;              \
            *(uint2*)(kh_b + 27648 + row * APB + lc * 2 + 8)  = lo;              \
        }                                                                        \
        if (t < 64) Msk[(st) * 64 + t] = pm;                                     \
    } while (0)

    // prologue: stage 0 filled, Q visible
    AT_LDG(0);
    __syncthreads();                   // Q smem writes visible for hoist

    // ---- hoist Q fragments into registers (chunk-invariant) ----
    uint32_t qh_r[2][4][4], ql_r[2][4][4];   // [mt][ks][frag]
    #pragma unroll
    for (int mt = 0; mt < 2; mt++)
        #pragma unroll
        for (int ks = 0; ks < 4; ks++) {
            uint32_t off = a_roff + mt * 16 * APB + ks * 32;
            ldsm_x4(qh_r[mt][ks], s0 + AQHI + off);
            ldsm_x4(ql_r[mt][ks], s0 + AQLO + off);
        }

    AT_STS(0);
    __syncthreads();

    float oacc[2][8][4];
    #pragma unroll
    for (int mt = 0; mt < 2; mt++)
        #pragma unroll
        for (int nt = 0; nt < 8; nt++)
            #pragma unroll
            for (int j = 0; j < 4; j++) oacc[mt][nt][j] = 0.f;

    for (int c = 0; c < 32; c++) {
        const int kb = c * 64;
        const int st = c & 1;
        const uint32_t sKh = s0 + ASKV + st * ASTG;
        const uint32_t sKl = sKh + 9216;
        const uint32_t sVh = sKh + 18432;
        const uint32_t sVl = sKh + 27648;

        if (c < 31) AT_LDG(c + 1);     // issue next chunk's loads now

        // ---- S = Q K^T (32q x 32k per warp), x4-paired K loads ----
        float sc[2][4][4];
        #pragma unroll
        for (int mt = 0; mt < 2; mt++)
            #pragma unroll
            for (int nf = 0; nf < 4; nf++)
                #pragma unroll
                for (int j = 0; j < 4; j++) sc[mt][nf][j] = 0.f;

        #pragma unroll
        for (int ks = 0; ks < 4; ks++) {
            #pragma unroll
            for (int nfp = 0; nfp < 2; nfp++) {
                uint32_t boff = b_roff4 + nfp * 16 * APB + ks * 32;
                uint32_t kh4[4], kl4[4];
                ldsm_x4(kh4, sKh + boff);
                ldsm_x4(kl4, sKl + boff);
                #pragma unroll
                for (int hh = 0; hh < 2; hh++) {
                    int nf = nfp * 2 + hh;
                    #pragma unroll
                    for (int mt = 0; mt < 2; mt++) {
                        mma16816(sc[mt][nf], qh_r[mt][ks], &kh4[hh * 2]);
                        mma16816(sc[mt][nf], qh_r[mt][ks], &kl4[hh * 2]);
                        mma16816(sc[mt][nf], ql_r[mt][ks], &kh4[hh * 2]);
                    }
                }
            }
        }

        // ---- epilogue: mask+exp, row sums, attn store, P frags ----
        uint32_t phi[2][2][4], plo[2][2][4];
        #pragma unroll
        for (int mt = 0; mt < 2; mt++) {
            float rs0 = 0.f, rs1 = 0.f;
            #pragma unroll
            for (int nf = 0; nf < 4; nf++) {
                int col = kw * 32 + nf * 8 + ec;
                int m0 = Msk[st * 64 + col], m1 = Msk[st * 64 + col + 1];
                float p00 = m0 ? __expf(sc[mt][nf][0]) : 0.f;
                float p01 = m1 ? __expf(sc[mt][nf][1]) : 0.f;
                float p10 = m0 ? __expf(sc[mt][nf][2]) : 0.f;
                float p11 = m1 ? __expf(sc[mt][nf][3]) : 0.f;
                rs0 += p00 + p01; rs1 += p10 + p11;
                if (attn) {
                    int q = q0 + qw * 32 + mt * 16 + er;
                    size_t ro = ((size_t)bh * S_ + q) * S_ + kb + col;
                    *(float2*)&attn[ro]          = make_float2(p00, p01);
                    *(float2*)&attn[ro + 8 * S_] = make_float2(p10, p11);
                }
                int kf = nf >> 1, hf = (nf & 1) * 2;
                float h00 = bf_round(p00), h01 = bf_round(p01);
                float h10 = bf_round(p10), h11 = bf_round(p11);
                phi[mt][kf][hf]     = packbf(h00, h01);
                phi[mt][kf][hf + 1] = packbf(h10, h11);
                plo[mt][kf][hf]     = packbf(p00 - h00, p01 - h01);
                plo[mt][kf][hf + 1] = packbf(p10 - h10, p11 - h11);
            }
            rs0 += __shfl_xor_sync(0xffffffffu, rs0, 1);
            rs0 += __shfl_xor_sync(0xffffffffu, rs0, 2);
            rs1 += __shfl_xor_sync(0xffffffffu, rs1, 1);
            rs1 += __shfl_xor_sync(0xffffffffu, rs1, 2);
            if ((lane & 3) == 0) {
                int q = qw * 32 + mt * 16 + er;
                Lpart[kw * 128 + q]     += rs0;
                Lpart[kw * 128 + q + 8] += rs1;
            }
        }

        // ---- O += P V, x4-paired (trans) V loads ----
        #pragma unroll
        for (int kf = 0; kf < 2; kf++) {
            #pragma unroll
            for (int np = 0; np < 4; np++) {
                uint32_t voff = v_roff4 + kf * 16 * APB + np * 32;
                uint32_t vh4[4], vl4[4];
                ldsm_x4t(vh4, sVh + voff);
                ldsm_x4t(vl4, sVl + voff);
                #pragma unroll
                for (int hh = 0; hh < 2; hh++) {
                    int nf2 = np * 2 + hh;
                    #pragma unroll
                    for (int mt = 0; mt < 2; mt++) {
                        mma16816(oacc[mt][nf2], phi[mt][kf], &vh4[hh * 2]);
                        mma16816(oacc[mt][nf2], phi[mt][kf], &vl4[hh * 2]);
                        mma16816(oacc[mt][nf2], plo[mt][kf], &vh4[hh * 2]);
                    }
                }
            }
        }

        // ---- store prefetched chunk into the OTHER stage, one barrier ----
        if (c < 31) AT_STS((c + 1) & 1);
        __syncthreads();
    }

    // ---- reduce O across the 2 k-warps via smem, normalize, write ----
    float* Ored = (float*)(ash + ASKV);        // reuse stage area
    if (kw == 1) {
        #pragma unroll
        for (int mt = 0; mt < 2; mt++)
            #pragma unroll
            for (int nf2 = 0; nf2 < 8; nf2++) {
                int q = qw * 32 + mt * 16 + er, d = nf2 * 8 + ec;
                *(float2*)&Ored[q * 68 + d]       = make_float2(oacc[mt][nf2][0], oacc[mt][nf2][1]);
                *(float2*)&Ored[(q + 8) * 68 + d] = make_float2(oacc[mt][nf2][2], oacc[mt][nf2][3]);
            }
    }
    __syncthreads();
    if (kw == 0) {
        #pragma unroll
        for (int mt = 0; mt < 2; mt++) {
            int qA = qw * 32 + mt * 16 + er;
            float invA = 1.f / (Lpart[qA] + Lpart[128 + qA]);
            float invB = 1.f / (Lpart[qA + 8] + Lpart[128 + qA + 8]);
            #pragma unroll
            for (int nf2 = 0; nf2 < 8; nf2++) {
                int d = nf2 * 8 + ec;
                float2 oA = *(float2*)&Ored[qA * 68 + d];
                float2 oB = *(float2*)&Ored[(qA + 8) * 68 + d];
                oA.x = (oA.x + oacc[mt][nf2][0]) * invA;
                oA.y = (oA.y + oacc[mt][nf2][1]) * invA;
                oB.x = (oB.x + oacc[mt][nf2][2]) * invB;
                oB.y = (oB.y + oacc[mt][nf2][3]) * invB;
                size_t oo = ((size_t)b * S_ + q0 + qA) * D_ + h * 64 + d;
                *(float2*)&Ctx[oo]          = oA;
                *(float2*)&Ctx[oo + 8 * D_] = oB;
            }
        }
    }
    if (t < 128) Lout[(size_t)bh * S_ + q0 + t] = Lpart[t] + Lpart[128 + t];
}

// ===========================================================================
extern "C" void kernel_launch(void* const* d_in, const int* in_sizes, int n_in,
                              void* d_out, int out_size)
{
    const float* query = (const float*)d_in[0];
    const float* key   = (const float*)d_in[1];
    const float* value = (const float*)d_in[2];
    const int*   mask  = (const int*)d_in[3];
    const float* W_Q   = (const float*)d_in[4];
    const float* W_K   = (const float*)d_in[5];
    const float* W_V   = (const float*)d_in[6];
    const float* W_O   = (const float*)d_in[7];

    float* out = (float*)d_out;
    bool hasAttn = (out_size >= OUT_ELEMS + ATT_ELEMS);
    float* attn = hasAttn ? (out + OUT_ELEMS) : nullptr;

    float *gq, *gk, *gv, *gc, *gl;
    cudaGetSymbolAddress((void**)&gq, g_Q);
    cudaGetSymbolAddress((void**)&gk, g_K);
    cudaGetSymbolAddress((void**)&gv, g_V);
    cudaGetSymbolAddress((void**)&gc, g_C);
    cudaGetSymbolAddress((void**)&gl, g_L);

    static cudaStream_t s2 = nullptr;
    static cudaEvent_t evFork = nullptr, evJoin = nullptr;
    if (s2 == nullptr) {
        cudaStreamCreateWithFlags(&s2, cudaStreamNonBlocking);
        cudaEventCreateWithFlags(&evFork, cudaEventDisableTiming);
        cudaEventCreateWithFlags(&evJoin, cudaEventDisableTiming);
        cudaFuncSetAttribute((const void*)attn_mma,
                             cudaFuncAttributeMaxDynamicSharedMemorySize, AT_SMEM);
        cudaFuncSetAttribute((const void*)qkv_gemm,
                             cudaFuncAttributeMaxDynamicSharedMemorySize, GT_SMEM);
        cudaFuncSetAttribute((const void*)wo_gemm,
                             cudaFuncAttributeMaxDynamicSharedMemorySize, GT_SMEM);
    }

    qkv_gemm<<<dim3(8, 32, 3), 256, GT_SMEM>>>(query, key, value,
                                               W_Q, W_K, W_V, gq, gk, gv);
    attn_mma<<<dim3(16, 16, 2), 256, AT_SMEM>>>(gq, gk, gv, mask, attn, gc, gl);

    if (hasAttn) {
        // fork: rescale (DRAM-bound) on s2, W_O GEMM (tensor-bound) on main
        cudaEventRecord(evFork, 0);
        cudaStreamWaitEvent(s2, evFork, 0);
        rescale_kernel<<<2048, 256, 0, s2>>>(attn, gl);
        wo_gemm<<<dim3(8, 32), 256, GT_SMEM>>>(gc, W_O, out);
        cudaEventRecord(evJoin, s2);
        cudaStreamWaitEvent((cudaStream_t)0, evJoin, 0);
    } else {
        wo_gemm<<<dim3(8, 32), 256, GT_SMEM>>>(gc, W_O, out);
    }
}